// round 7
// baseline (speedup 1.0000x reference)
#include <cuda_runtime.h>
#include <cuda_bf16.h>
#include <cstdint>

// ---------------------------------------------------------------------------
// Spk_Attention: B=512, N=256, H=512. sm_103 plain target -> mma.sync bf16
// m16n8k16 3xBF16 compensation, separate hi/lo planes, ldmatrix.x4,
// 3-stage k16 cp.async pipeline (2 loads always in flight).
// ---------------------------------------------------------------------------

#define Bsz 512
#define Nn  256
#define Hh  512

__device__ float g_Wresp[Bsz * Hh];
__device__ float g_rx[Bsz * Hh];
__device__ float g_scores_part[4 * Bsz * Nn];
__device__ float g_resps[Bsz * Hh];
__device__ __nv_bfloat16 g_Ahi[(size_t)Bsz * Nn * Hh];
__device__ __nv_bfloat16 g_Alo[(size_t)Bsz * Nn * Hh];
__device__ __nv_bfloat16 g_Bhi[Hh * Hh];
__device__ __nv_bfloat16 g_Blo[Hh * Hh];

// ---------------- helpers --------------------------------------------------
__device__ __forceinline__ float tanh_fast(float x) {
    float y;
    asm("tanh.approx.f32 %0, %1;" : "=f"(y) : "f"(x));
    return y;
}
__device__ __forceinline__ uint32_t smem_u32(const void* p) {
    uint32_t a;
    asm("{ .reg .u64 t; cvta.to.shared.u64 t, %1; cvt.u32.u64 %0, t; }"
        : "=r"(a) : "l"(p));
    return a;
}
__device__ __forceinline__ void cp16(uint32_t dst, const void* src) {
    asm volatile("cp.async.cg.shared.global [%0], [%1], 16;"
                 :: "r"(dst), "l"(src) : "memory");
}
__device__ __forceinline__ void ldsm4(uint32_t* r, uint32_t addr) {
    asm volatile("ldmatrix.sync.aligned.m8n8.x4.shared.b16 {%0,%1,%2,%3}, [%4];"
                 : "=r"(r[0]), "=r"(r[1]), "=r"(r[2]), "=r"(r[3]) : "r"(addr));
}
__device__ __forceinline__ void mma_bf16(float* d, const uint32_t* a,
                                         uint32_t b0, uint32_t b1) {
    asm volatile(
        "mma.sync.aligned.m16n8k16.row.col.f32.bf16.bf16.f32 "
        "{%0,%1,%2,%3}, {%4,%5,%6,%7}, {%8,%9}, {%0,%1,%2,%3};"
        : "+f"(d[0]), "+f"(d[1]), "+f"(d[2]), "+f"(d[3])
        : "r"(a[0]), "r"(a[1]), "r"(a[2]), "r"(a[3]), "r"(b0), "r"(b1));
}
__device__ __forceinline__ void split1(float v, __nv_bfloat16& h,
                                       __nv_bfloat16& l) {
    h = __float2bfloat16(v);
    l = __float2bfloat16(v - __bfloat162float(h));
}

// ---------------------------------------------------------------------------
// pre-split kernels
// ---------------------------------------------------------------------------
__global__ __launch_bounds__(256)
void split_spk(const float* __restrict__ A,
               __nv_bfloat16* __restrict__ Ahi,
               __nv_bfloat16* __restrict__ Alo) {
    const size_t j = (size_t)blockIdx.x * 256 + threadIdx.x;
    const float2 v = ((const float2*)A)[j];
    __nv_bfloat162 h2, l2;
    split1(v.x, h2.x, l2.x);
    split1(v.y, h2.y, l2.y);
    ((__nv_bfloat162*)Ahi)[j] = h2;
    ((__nv_bfloat162*)Alo)[j] = l2;
}

__global__ __launch_bounds__(512)
void split_ws(const float* __restrict__ Ws,
              __nv_bfloat16* __restrict__ Bhi,
              __nv_bfloat16* __restrict__ Blo) {
    const int p = blockIdx.x;
    const int n = threadIdx.x;
    __nv_bfloat162 h2, l2;
    split1(Ws[(2 * p) * Hh + n],     h2.x, l2.x);
    split1(Ws[(2 * p + 1) * Hh + n], h2.y, l2.y);
    ((__nv_bfloat162*)Bhi)[(size_t)n * (Hh / 2) + p] = h2;
    ((__nv_bfloat162*)Blo)[(size_t)n * (Hh / 2) + p] = l2;
}

// ---------------------------------------------------------------------------
// score kernel: CTA = 128 rows x 128 cols, K = 512, 32 k16-tiles, 3 stages.
// grid = (4 col-chunks, 1024 row-blocks): concurrent CTAs share A in L2.
// SMEM plane row = 16 bf16 = 32B data, 48B stride (conflict-free ldsm).
// ---------------------------------------------------------------------------
#define ROWB    48
#define PLANE_W (128 * 12)          // words per plane (12w = 48B)
#define STG_W   (4 * PLANE_W)       // Ahi Alo Bhi Blo = 24KB
#define NSTG    3
#define SM_W    (NSTG * STG_W + 512)
#define SM_BYTES (SM_W * 4)

__global__ __launch_bounds__(256, 2)
void score_mma(const __nv_bfloat16* __restrict__ Ahi,
               const __nv_bfloat16* __restrict__ Alo,
               const __nv_bfloat16* __restrict__ Bhi,
               const __nv_bfloat16* __restrict__ Blo,
               const float* __restrict__ Wresp,
               const float* __restrict__ wvec,
               float* __restrict__ scores_part)
{
    extern __shared__ uint32_t smw[];
    float* WRs = (float*)(smw + NSTG * STG_W);
    float* WVs = WRs + 128;
    float* sp2 = WVs + 128;   // [2][128]

    const int tid  = threadIdx.x;
    const int lane = tid & 31, wid = tid >> 5;
    const int wm = wid & 3, wn = wid >> 2;     // 4 x 2 warp grid
    const int g  = lane >> 2, tg = lane & 3;
    const int col0 = blockIdx.x * 128;
    const int row0 = blockIdx.y * 128;
    const int b    = row0 >> 8;

    if (tid < 128) {
        WRs[tid] = Wresp[b * Hh + col0 + tid];
        WVs[tid] = wvec[col0 + tid];
    }

    const uint32_t sbase = smem_u32(smw);

    // ldmatrix lane offsets (bytes) within a plane tile
    const uint32_t a_off = (((lane & 7) | (((lane >> 3) & 1) << 3)) * ROWB)
                           + ((lane >> 4) << 4);
    const uint32_t b_off = (((lane & 7) | (((lane >> 4) & 1) << 3)) * ROWB)
                           + (((lane >> 3) & 1) << 4);

    // stage loader: 4 planes x 128 rows x 32B = 1024 16B-chunks
    auto load_stage = [&](int kk, int slot) {
        const uint32_t db = sbase + (uint32_t)slot * (STG_W * 4);
        #pragma unroll
        for (int i = 0; i < 4; i++) {
            const int idx = tid + 256 * i;
            const int plane = idx >> 8;          // warp-uniform
            const int r = (idx >> 1) & 127;
            const int c = idx & 1;
            const __nv_bfloat16* src;
            if (plane == 0)
                src = Ahi + (size_t)(row0 + r) * Hh + kk * 16 + c * 8;
            else if (plane == 1)
                src = Alo + (size_t)(row0 + r) * Hh + kk * 16 + c * 8;
            else if (plane == 2)
                src = Bhi + (size_t)(col0 + r) * Hh + kk * 16 + c * 8;
            else
                src = Blo + (size_t)(col0 + r) * Hh + kk * 16 + c * 8;
            cp16(db + plane * (PLANE_W * 4) + r * ROWB + c * 16, src);
        }
        asm volatile("cp.async.commit_group;" ::: "memory");
    };

    load_stage(0, 0);
    load_stage(1, 1);
    load_stage(2, 2);

    float acc[2][8][4];
    #pragma unroll
    for (int mt = 0; mt < 2; mt++)
        #pragma unroll
        for (int nt = 0; nt < 8; nt++)
            #pragma unroll
            for (int c = 0; c < 4; c++) acc[mt][nt][c] = 0.0f;

    int slot = 0;
    #pragma unroll 1
    for (int kk = 0; kk < 32; kk++) {
        if (kk < 30)       asm volatile("cp.async.wait_group 2;" ::: "memory");
        else if (kk == 30) asm volatile("cp.async.wait_group 1;" ::: "memory");
        else               asm volatile("cp.async.wait_group 0;" ::: "memory");
        __syncthreads();

        const uint32_t stg  = sbase + (uint32_t)slot * (STG_W * 4);
        const uint32_t pAhi = stg;
        const uint32_t pAlo = stg + PLANE_W * 4;
        const uint32_t pBhi = stg + 2 * PLANE_W * 4;
        const uint32_t pBlo = stg + 3 * PLANE_W * 4;

        uint32_t ahi[2][4], alo[2][4];
        #pragma unroll
        for (int mt = 0; mt < 2; mt++) {
            const uint32_t ro = (wm * 32 + mt * 16) * ROWB;
            ldsm4(ahi[mt], pAhi + ro + a_off);
            ldsm4(alo[mt], pAlo + ro + a_off);
        }
        #pragma unroll
        for (int ntp = 0; ntp < 4; ntp++) {
            const uint32_t ro = (wn * 64 + ntp * 16) * ROWB;
            uint32_t bh[4], bl[4];
            ldsm4(bh, pBhi + ro + b_off);
            ldsm4(bl, pBlo + ro + b_off);
            #pragma unroll
            for (int half = 0; half < 2; half++) {
                const int nt = ntp * 2 + half;
                const uint32_t b0h = bh[half * 2], b1h = bh[half * 2 + 1];
                const uint32_t b0l = bl[half * 2], b1l = bl[half * 2 + 1];
                #pragma unroll
                for (int mt = 0; mt < 2; mt++) {
                    mma_bf16(acc[mt][nt], ahi[mt], b0l, b1l);  // hi*lo
                    mma_bf16(acc[mt][nt], alo[mt], b0h, b1h);  // lo*hi
                    mma_bf16(acc[mt][nt], ahi[mt], b0h, b1h);  // hi*hi
                }
            }
        }
        __syncthreads();
        if (kk + 3 < 32) load_stage(kk + 3, slot);
        slot = (slot == 2) ? 0 : slot + 1;
    }

    // epilogue: tanh + dot(w), deterministic reduce over 128 cols
    #pragma unroll
    for (int mt = 0; mt < 2; mt++) {
        float plo = 0.0f, phi = 0.0f;
        #pragma unroll
        for (int nt = 0; nt < 8; nt++) {
            const int c0 = wn * 64 + nt * 8 + 2 * tg;
            const int c1 = c0 + 1;
            plo += tanh_fast(acc[mt][nt][0] + WRs[c0]) * WVs[c0]
                 + tanh_fast(acc[mt][nt][1] + WRs[c1]) * WVs[c1];
            phi += tanh_fast(acc[mt][nt][2] + WRs[c0]) * WVs[c0]
                 + tanh_fast(acc[mt][nt][3] + WRs[c1]) * WVs[c1];
        }
        plo += __shfl_xor_sync(0xFFFFFFFFu, plo, 1);
        plo += __shfl_xor_sync(0xFFFFFFFFu, plo, 2);
        phi += __shfl_xor_sync(0xFFFFFFFFu, phi, 1);
        phi += __shfl_xor_sync(0xFFFFFFFFu, phi, 2);
        if (tg == 0) {
            sp2[wn * 128 + wm * 32 + mt * 16 + g]     = plo;
            sp2[wn * 128 + wm * 32 + mt * 16 + 8 + g] = phi;
        }
    }
    __syncthreads();
    if (tid < 128)
        scores_part[(size_t)blockIdx.x * (Bsz * Nn) + row0 + tid] =
            sp2[tid] + sp2[128 + tid];
}

// ---------------------------------------------------------------------------
// Per-batch softmax + resp_s = alpha . spk_emb  (4-way ILP accumulation)
// ---------------------------------------------------------------------------
__global__ __launch_bounds__(512)
void softmax_weight_kernel(const float* __restrict__ scores_part,
                           const float* __restrict__ mask,
                           const float* __restrict__ emb,
                           float* __restrict__ alpha_out,
                           float* __restrict__ resps)
{
    const int b = blockIdx.x;
    const int tid = threadIdx.x;
    __shared__ float sa[256];
    __shared__ float red[512];

    float t = -1e30f;
    if (tid < Nn) {
        const size_t i = (size_t)b * Nn + tid;
        float s = scores_part[i];
        s += scores_part[(size_t)(Bsz * Nn) + i];
        s += scores_part[(size_t)(2 * Bsz * Nn) + i];
        s += scores_part[(size_t)(3 * Bsz * Nn) + i];
        t = s * mask[i];
    }

    red[tid] = t; __syncthreads();
    #pragma unroll
    for (int s = 256; s > 0; s >>= 1) {
        if (tid < s) red[tid] = fmaxf(red[tid], red[tid + s]);
        __syncthreads();
    }
    const float m = red[0];
    __syncthreads();

    const float e = (tid < Nn) ? __expf(t - m) : 0.0f;
    red[tid] = e; __syncthreads();
    #pragma unroll
    for (int s = 256; s > 0; s >>= 1) {
        if (tid < s) red[tid] += red[tid + s];
        __syncthreads();
    }
    const float a = e / red[0];

    if (tid < Nn) {
        alpha_out[(size_t)b * Nn + tid] = a;
        sa[tid] = a;
    }
    __syncthreads();

    const float* eb = emb + (size_t)b * Nn * Hh;
    float a0 = 0.0f, a1 = 0.0f, a2 = 0.0f, a3 = 0.0f;
    #pragma unroll 2
    for (int n = 0; n < Nn; n += 4) {
        a0 = fmaf(sa[n],     eb[(size_t)(n    ) * Hh + tid], a0);
        a1 = fmaf(sa[n + 1], eb[(size_t)(n + 1) * Hh + tid], a1);
        a2 = fmaf(sa[n + 2], eb[(size_t)(n + 2) * Hh + tid], a2);
        a3 = fmaf(sa[n + 3], eb[(size_t)(n + 3) * Hh + tid], a3);
    }
    resps[b * Hh + tid] = (a0 + a1) + (a2 + a3);
}

// ---------------------------------------------------------------------------
// Fused dual small GEMM: z=0: Wresp = tr @ Wr ; z=1: rx = tr @ Wx^T
// 64x64 CTA tile, 4x4 microtile, 256 threads.
// ---------------------------------------------------------------------------
__global__ __launch_bounds__(256)
void gemm_dual(const float* __restrict__ A,
               const float* __restrict__ Wr,
               const float* __restrict__ Wx,
               float* __restrict__ outWresp,
               float* __restrict__ outRx)
{
    __shared__ float As[16][68];
    __shared__ float Bs[16][68];
    const int tid = threadIdx.x;
    const int tx = tid & 15, ty = tid >> 4;
    const int col0 = blockIdx.x * 64, row0 = blockIdx.y * 64;
    const bool trans = (blockIdx.z == 1);
    const float* B = trans ? Wx : Wr;
    float* out = trans ? outRx : outWresp;

    float acc[4][4];
    #pragma unroll
    for (int i = 0; i < 4; i++)
        #pragma unroll
        for (int j = 0; j < 4; j++) acc[i][j] = 0.0f;

    for (int kt = 0; kt < 32; kt++) {
        const int k0 = kt * 16;
        {
            const int r = tid >> 2, k4 = (tid & 3) * 4;
            const float4 v = *(const float4*)&A[(size_t)(row0 + r) * Hh + k0 + k4];
            As[k4 + 0][r] = v.x; As[k4 + 1][r] = v.y;
            As[k4 + 2][r] = v.z; As[k4 + 3][r] = v.w;
        }
        if (trans) {
            const int c = tid >> 2, k4 = (tid & 3) * 4;
            const float4 v = *(const float4*)&B[(size_t)(col0 + c) * Hh + k0 + k4];
            Bs[k4 + 0][c] = v.x; Bs[k4 + 1][c] = v.y;
            Bs[k4 + 2][c] = v.z; Bs[k4 + 3][c] = v.w;
        } else {
            const int k = tid >> 4, c4 = (tid & 15) * 4;
            *(float4*)&Bs[k][c4] = *(const float4*)&B[(size_t)(k0 + k) * Hh + col0 + c4];
        }
        __syncthreads();

        #pragma unroll
        for (int k = 0; k < 16; k++) {
            float a[4], bb[4];
            #pragma unroll
            for (int i = 0; i < 4; i++) a[i]  = As[k][ty * 4 + i];
            #pragma unroll
            for (int j = 0; j < 4; j++) bb[j] = Bs[k][tx * 4 + j];
            #pragma unroll
            for (int i = 0; i < 4; i++)
                #pragma unroll
                for (int j = 0; j < 4; j++)
                    acc[i][j] = fmaf(a[i], bb[j], acc[i][j]);
        }
        __syncthreads();
    }

    #pragma unroll
    for (int i = 0; i < 4; i++)
        #pragma unroll
        for (int j = 0; j < 4; j++)
            out[(size_t)(row0 + ty * 4 + i) * Hh + col0 + tx * 4 + j] = acc[i][j];
}

// ---------------------------------------------------------------------------
// Final small GEMM: out = tanh(A @ Wp^T + Cadd)
// ---------------------------------------------------------------------------
__global__ __launch_bounds__(256)
void gemm_final(const float* __restrict__ A,
                const float* __restrict__ B,
                const float* __restrict__ Cadd,
                float* __restrict__ out)
{
    __shared__ float As[16][68];
    __shared__ float Bs[16][68];
    const int tid = threadIdx.x;
    const int tx = tid & 15, ty = tid >> 4;
    const int col0 = blockIdx.x * 64, row0 = blockIdx.y * 64;

    float acc[4][4];
    #pragma unroll
    for (int i = 0; i < 4; i++)
        #pragma unroll
        for (int j = 0; j < 4; j++) acc[i][j] = 0.0f;

    for (int kt = 0; kt < 32; kt++) {
        const int k0 = kt * 16;
        {
            const int r = tid >> 2, k4 = (tid & 3) * 4;
            const float4 v = *(const float4*)&A[(size_t)(row0 + r) * Hh + k0 + k4];
            As[k4 + 0][r] = v.x; As[k4 + 1][r] = v.y;
            As[k4 + 2][r] = v.z; As[k4 + 3][r] = v.w;
        }
        {
            const int c = tid >> 2, k4 = (tid & 3) * 4;
            const float4 v = *(const float4*)&B[(size_t)(col0 + c) * Hh + k0 + k4];
            Bs[k4 + 0][c] = v.x; Bs[k4 + 1][c] = v.y;
            Bs[k4 + 2][c] = v.z; Bs[k4 + 3][c] = v.w;
        }
        __syncthreads();

        #pragma unroll
        for (int k = 0; k < 16; k++) {
            float a[4], bb[4];
            #pragma unroll
            for (int i = 0; i < 4; i++) a[i]  = As[k][ty * 4 + i];
            #pragma unroll
            for (int j = 0; j < 4; j++) bb[j] = Bs[k][tx * 4 + j];
            #pragma unroll
            for (int i = 0; i < 4; i++)
                #pragma unroll
                for (int j = 0; j < 4; j++)
                    acc[i][j] = fmaf(a[i], bb[j], acc[i][j]);
        }
        __syncthreads();
    }

    #pragma unroll
    for (int i = 0; i < 4; i++)
        #pragma unroll
        for (int j = 0; j < 4; j++) {
            const size_t idx = (size_t)(row0 + ty * 4 + i) * Hh + col0 + tx * 4 + j;
            out[idx] = tanhf(acc[i][j] + Cadd[idx]);
        }
}

// ---------------------------------------------------------------------------
extern "C" void kernel_launch(void* const* d_in, const int* in_sizes, int n_in,
                              void* d_out, int out_size)
{
    const float* spk  = (const float*)d_in[0];
    const float* mask = (const float*)d_in[1];
    const float* tr   = (const float*)d_in[2];
    const float* Ws   = (const float*)d_in[3];
    const float* Wr   = (const float*)d_in[4];
    const float* w    = (const float*)d_in[5];
    const float* Wp   = (const float*)d_in[6];
    const float* Wx   = (const float*)d_in[7];

    float* out = (float*)d_out;
    float* resp_out  = out;
    float* alpha_out = out + Bsz * Hh;

    float *pWresp, *prx, *pspart, *presps;
    __nv_bfloat16 *pAhi, *pAlo, *pBhi, *pBlo;
    cudaGetSymbolAddress((void**)&pWresp, g_Wresp);
    cudaGetSymbolAddress((void**)&prx, g_rx);
    cudaGetSymbolAddress((void**)&pspart, g_scores_part);
    cudaGetSymbolAddress((void**)&presps, g_resps);
    cudaGetSymbolAddress((void**)&pAhi, g_Ahi);
    cudaGetSymbolAddress((void**)&pAlo, g_Alo);
    cudaGetSymbolAddress((void**)&pBhi, g_Bhi);
    cudaGetSymbolAddress((void**)&pBlo, g_Blo);

    static bool attr_set = false;
    if (!attr_set) {
        cudaFuncSetAttribute(score_mma,
                             cudaFuncAttributeMaxDynamicSharedMemorySize,
                             SM_BYTES);
        attr_set = true;
    }

    split_spk<<<(Bsz * Nn * Hh / 2) / 256, 256>>>(spk, pAhi, pAlo);
    split_ws<<<Hh / 2, Hh>>>(Ws, pBhi, pBlo);
    gemm_dual<<<dim3(8, 8, 2), 256>>>(tr, Wr, Wx, pWresp, prx);
    score_mma<<<dim3(4, 1024), 256, SM_BYTES>>>(pAhi, pAlo, pBhi, pBlo,
                                                pWresp, w, pspart);
    softmax_weight_kernel<<<Bsz, 512>>>(pspart, mask, spk, alpha_out, presps);
    gemm_final<<<dim3(8, 8), 256>>>(presps, Wp, prx, resp_out);
}

// round 8
// speedup vs baseline: 1.7895x; 1.7895x over previous
#include <cuda_runtime.h>
#include <cuda_bf16.h>
#include <cstdint>

// ---------------------------------------------------------------------------
// Spk_Attention: B=512, N=256, H=512. sm_103 plain target -> mma.sync bf16
// m16n8k16 3xBF16, hi/lo planes, ldmatrix.x4 with XOR-swizzled SMEM,
// 3-stage k32 cp.async pipeline, ONE __syncthreads per k-tile.
// ---------------------------------------------------------------------------

#define Bsz 512
#define Nn  256
#define Hh  512

__device__ float g_Wresp[Bsz * Hh];
__device__ float g_rx[Bsz * Hh];
__device__ float g_scores_part[4 * Bsz * Nn];
__device__ float g_resps[Bsz * Hh];
__device__ __nv_bfloat16 g_Ahi[(size_t)Bsz * Nn * Hh];
__device__ __nv_bfloat16 g_Alo[(size_t)Bsz * Nn * Hh];
__device__ __nv_bfloat16 g_Bhi[Hh * Hh];
__device__ __nv_bfloat16 g_Blo[Hh * Hh];

// ---------------- helpers --------------------------------------------------
__device__ __forceinline__ float tanh_fast(float x) {
    float y;
    asm("tanh.approx.f32 %0, %1;" : "=f"(y) : "f"(x));
    return y;
}
__device__ __forceinline__ uint32_t smem_u32(const void* p) {
    uint32_t a;
    asm("{ .reg .u64 t; cvta.to.shared.u64 t, %1; cvt.u32.u64 %0, t; }"
        : "=r"(a) : "l"(p));
    return a;
}
__device__ __forceinline__ void cp16(uint32_t dst, const void* src) {
    asm volatile("cp.async.cg.shared.global [%0], [%1], 16;"
                 :: "r"(dst), "l"(src) : "memory");
}
__device__ __forceinline__ void ldsm4(uint32_t* r, uint32_t addr) {
    asm volatile("ldmatrix.sync.aligned.m8n8.x4.shared.b16 {%0,%1,%2,%3}, [%4];"
                 : "=r"(r[0]), "=r"(r[1]), "=r"(r[2]), "=r"(r[3]) : "r"(addr));
}
__device__ __forceinline__ void mma_bf16(float* d, const uint32_t* a,
                                         uint32_t b0, uint32_t b1) {
    asm volatile(
        "mma.sync.aligned.m16n8k16.row.col.f32.bf16.bf16.f32 "
        "{%0,%1,%2,%3}, {%4,%5,%6,%7}, {%8,%9}, {%0,%1,%2,%3};"
        : "+f"(d[0]), "+f"(d[1]), "+f"(d[2]), "+f"(d[3])
        : "r"(a[0]), "r"(a[1]), "r"(a[2]), "r"(a[3]), "r"(b0), "r"(b1));
}
__device__ __forceinline__ void split1(float v, __nv_bfloat16& h,
                                       __nv_bfloat16& l) {
    h = __float2bfloat16(v);
    l = __float2bfloat16(v - __bfloat162float(h));
}
// XOR-swizzled byte offset of 16B chunk c in row r (64B rows, 4 chunks)
__device__ __forceinline__ uint32_t swz(uint32_t r, uint32_t c) {
    return r * 64u + ((c ^ ((r >> 1) & 3u)) << 4);
}

// ---------------------------------------------------------------------------
// pre-split kernels
// ---------------------------------------------------------------------------
__global__ __launch_bounds__(256)
void split_spk(const float* __restrict__ A,
               __nv_bfloat16* __restrict__ Ahi,
               __nv_bfloat16* __restrict__ Alo) {
    const size_t j = (size_t)blockIdx.x * 256 + threadIdx.x;
    const float2 v = ((const float2*)A)[j];
    __nv_bfloat162 h2, l2;
    split1(v.x, h2.x, l2.x);
    split1(v.y, h2.y, l2.y);
    ((__nv_bfloat162*)Ahi)[j] = h2;
    ((__nv_bfloat162*)Alo)[j] = l2;
}

__global__ __launch_bounds__(512)
void split_ws(const float* __restrict__ Ws,
              __nv_bfloat16* __restrict__ Bhi,
              __nv_bfloat16* __restrict__ Blo) {
    const int p = blockIdx.x;
    const int n = threadIdx.x;
    __nv_bfloat162 h2, l2;
    split1(Ws[(2 * p) * Hh + n],     h2.x, l2.x);
    split1(Ws[(2 * p + 1) * Hh + n], h2.y, l2.y);
    ((__nv_bfloat162*)Bhi)[(size_t)n * (Hh / 2) + p] = h2;
    ((__nv_bfloat162*)Blo)[(size_t)n * (Hh / 2) + p] = l2;
}

// ---------------------------------------------------------------------------
// score kernel: CTA = 128 rows x 128 cols, K = 512 in 16 k32-tiles, 3 stages.
// grid = (4 col-chunks, 1024 row-blocks). SMEM: XOR swizzle, 64B rows.
// Single __syncthreads per tile (CUTLASS multistage ordering).
// ---------------------------------------------------------------------------
#define PLANE_W 2048u                 // words: 128 rows x 64B
#define STG_W   (4u * PLANE_W)        // Ahi Alo Bhi Blo = 32KB
#define NSTG    3
#define SM_W    (NSTG * STG_W + 512)
#define SM_BYTES (SM_W * 4)

__global__ __launch_bounds__(256, 2)
void score_mma(const __nv_bfloat16* __restrict__ Ahi,
               const __nv_bfloat16* __restrict__ Alo,
               const __nv_bfloat16* __restrict__ Bhi,
               const __nv_bfloat16* __restrict__ Blo,
               const float* __restrict__ Wresp,
               const float* __restrict__ wvec,
               float* __restrict__ scores_part)
{
    extern __shared__ uint32_t smw[];
    float* WRs = (float*)(smw + NSTG * STG_W);
    float* WVs = WRs + 128;
    float* sp2 = WVs + 128;   // [2][128]

    const int tid  = threadIdx.x;
    const int lane = tid & 31, wid = tid >> 5;
    const int wm = wid & 3, wn = wid >> 2;     // 4 x 2 warp grid
    const int g  = lane >> 2, tg = lane & 3;
    const int col0 = blockIdx.x * 128;
    const int row0 = blockIdx.y * 128;
    const int b    = row0 >> 8;

    if (tid < 128) {
        WRs[tid] = Wresp[b * Hh + col0 + tid];
        WVs[tid] = wvec[col0 + tid];
    }

    const uint32_t sbase = smem_u32(smw);

    // ldmatrix fragment row/chunk components (lane-dependent)
    const uint32_t a_row = (lane & 7) | (((lane >> 3) & 1) << 3);  // 0..15
    const uint32_t a_chk = (lane >> 4) & 1;                        // 0/1
    const uint32_t b_row = (lane & 7) | (((lane >> 4) & 1) << 3);
    const uint32_t b_chk = (lane >> 3) & 1;

    // stage loader: 4 planes x 128 rows x 64B = 2048 16B-chunks, 8 per thread
    auto load_stage = [&](int kk, int slot) {
        const uint32_t db = sbase + (uint32_t)slot * (STG_W * 4);
        #pragma unroll
        for (int i = 0; i < 8; i++) {
            const int idx = tid + 256 * i;
            const int plane = idx >> 9;          // warp-uniform
            const uint32_t r = (idx >> 2) & 127;
            const uint32_t c = idx & 3;
            const __nv_bfloat16* src;
            if (plane == 0)
                src = Ahi + (size_t)(row0 + r) * Hh + kk * 32 + c * 8;
            else if (plane == 1)
                src = Alo + (size_t)(row0 + r) * Hh + kk * 32 + c * 8;
            else if (plane == 2)
                src = Bhi + (size_t)(col0 + r) * Hh + kk * 32 + c * 8;
            else
                src = Blo + (size_t)(col0 + r) * Hh + kk * 32 + c * 8;
            cp16(db + plane * (PLANE_W * 4) + swz(r, c), src);
        }
        asm volatile("cp.async.commit_group;" ::: "memory");
    };

    // prologue: 2 tiles in flight
    load_stage(0, 0);
    load_stage(1, 1);

    float acc[2][8][4];
    #pragma unroll
    for (int mt = 0; mt < 2; mt++)
        #pragma unroll
        for (int nt = 0; nt < 8; nt++)
            #pragma unroll
            for (int c = 0; c < 4; c++) acc[mt][nt][c] = 0.0f;

    #pragma unroll 1
    for (int kk = 0; kk < 16; kk++) {
        if (kk < 15) asm volatile("cp.async.wait_group 1;" ::: "memory");
        else         asm volatile("cp.async.wait_group 0;" ::: "memory");
        __syncthreads();   // single barrier per tile

        // issue next load into the slot consumed LAST iteration
        if (kk + 2 < 16) load_stage(kk + 2, (kk + 2) % 3);

        const uint32_t stg  = sbase + (uint32_t)(kk % 3) * (STG_W * 4);
        const uint32_t pAhi = stg;
        const uint32_t pAlo = stg + PLANE_W * 4;
        const uint32_t pBhi = stg + 2 * PLANE_W * 4;
        const uint32_t pBlo = stg + 3 * PLANE_W * 4;

        #pragma unroll
        for (int ks = 0; ks < 2; ks++) {
            uint32_t ahi[2][4], alo[2][4];
            #pragma unroll
            for (int mt = 0; mt < 2; mt++) {
                const uint32_t r = wm * 32 + mt * 16 + a_row;
                const uint32_t off = swz(r, ks * 2 + a_chk);
                ldsm4(ahi[mt], pAhi + off);
                ldsm4(alo[mt], pAlo + off);
            }
            #pragma unroll
            for (int ntp = 0; ntp < 4; ntp++) {
                const uint32_t r = wn * 64 + ntp * 16 + b_row;
                const uint32_t off = swz(r, ks * 2 + b_chk);
                uint32_t bh[4], bl[4];
                ldsm4(bh, pBhi + off);
                ldsm4(bl, pBlo + off);
                #pragma unroll
                for (int half = 0; half < 2; half++) {
                    const int nt = ntp * 2 + half;
                    const uint32_t b0h = bh[half * 2], b1h = bh[half * 2 + 1];
                    const uint32_t b0l = bl[half * 2], b1l = bl[half * 2 + 1];
                    #pragma unroll
                    for (int mt = 0; mt < 2; mt++) {
                        mma_bf16(acc[mt][nt], ahi[mt], b0l, b1l);  // hi*lo
                        mma_bf16(acc[mt][nt], alo[mt], b0h, b1h);  // lo*hi
                        mma_bf16(acc[mt][nt], ahi[mt], b0h, b1h);  // hi*hi
                    }
                }
            }
        }
    }

    // epilogue: tanh + dot(w), deterministic reduce over 128 cols
    #pragma unroll
    for (int mt = 0; mt < 2; mt++) {
        float plo = 0.0f, phi = 0.0f;
        #pragma unroll
        for (int nt = 0; nt < 8; nt++) {
            const int c0 = wn * 64 + nt * 8 + 2 * tg;
            const int c1 = c0 + 1;
            plo += tanh_fast(acc[mt][nt][0] + WRs[c0]) * WVs[c0]
                 + tanh_fast(acc[mt][nt][1] + WRs[c1]) * WVs[c1];
            phi += tanh_fast(acc[mt][nt][2] + WRs[c0]) * WVs[c0]
                 + tanh_fast(acc[mt][nt][3] + WRs[c1]) * WVs[c1];
        }
        plo += __shfl_xor_sync(0xFFFFFFFFu, plo, 1);
        plo += __shfl_xor_sync(0xFFFFFFFFu, plo, 2);
        phi += __shfl_xor_sync(0xFFFFFFFFu, phi, 1);
        phi += __shfl_xor_sync(0xFFFFFFFFu, phi, 2);
        if (tg == 0) {
            sp2[wn * 128 + wm * 32 + mt * 16 + g]     = plo;
            sp2[wn * 128 + wm * 32 + mt * 16 + 8 + g] = phi;
        }
    }
    __syncthreads();
    if (tid < 128)
        scores_part[(size_t)blockIdx.x * (Bsz * Nn) + row0 + tid] =
            sp2[tid] + sp2[128 + tid];
}

// ---------------------------------------------------------------------------
// Per-batch softmax + resp_s = alpha . spk_emb  (4-way ILP)
// ---------------------------------------------------------------------------
__global__ __launch_bounds__(512)
void softmax_weight_kernel(const float* __restrict__ scores_part,
                           const float* __restrict__ mask,
                           const float* __restrict__ emb,
                           float* __restrict__ alpha_out,
                           float* __restrict__ resps)
{
    const int b = blockIdx.x;
    const int tid = threadIdx.x;
    __shared__ float sa[256];
    __shared__ float red[512];

    float t = -1e30f;
    if (tid < Nn) {
        const size_t i = (size_t)b * Nn + tid;
        float s = scores_part[i];
        s += scores_part[(size_t)(Bsz * Nn) + i];
        s += scores_part[(size_t)(2 * Bsz * Nn) + i];
        s += scores_part[(size_t)(3 * Bsz * Nn) + i];
        t = s * mask[i];
    }

    red[tid] = t; __syncthreads();
    #pragma unroll
    for (int s = 256; s > 0; s >>= 1) {
        if (tid < s) red[tid] = fmaxf(red[tid], red[tid + s]);
        __syncthreads();
    }
    const float m = red[0];
    __syncthreads();

    const float e = (tid < Nn) ? __expf(t - m) : 0.0f;
    red[tid] = e; __syncthreads();
    #pragma unroll
    for (int s = 256; s > 0; s >>= 1) {
        if (tid < s) red[tid] += red[tid + s];
        __syncthreads();
    }
    const float a = e / red[0];

    if (tid < Nn) {
        alpha_out[(size_t)b * Nn + tid] = a;
        sa[tid] = a;
    }
    __syncthreads();

    const float* eb = emb + (size_t)b * Nn * Hh;
    float a0 = 0.0f, a1 = 0.0f, a2 = 0.0f, a3 = 0.0f;
    #pragma unroll 2
    for (int n = 0; n < Nn; n += 4) {
        a0 = fmaf(sa[n],     eb[(size_t)(n    ) * Hh + tid], a0);
        a1 = fmaf(sa[n + 1], eb[(size_t)(n + 1) * Hh + tid], a1);
        a2 = fmaf(sa[n + 2], eb[(size_t)(n + 2) * Hh + tid], a2);
        a3 = fmaf(sa[n + 3], eb[(size_t)(n + 3) * Hh + tid], a3);
    }
    resps[b * Hh + tid] = (a0 + a1) + (a2 + a3);
}

// ---------------------------------------------------------------------------
// Fused dual small GEMM: z=0: Wresp = tr @ Wr ; z=1: rx = tr @ Wx^T
// ---------------------------------------------------------------------------
__global__ __launch_bounds__(256)
void gemm_dual(const float* __restrict__ A,
               const float* __restrict__ Wr,
               const float* __restrict__ Wx,
               float* __restrict__ outWresp,
               float* __restrict__ outRx)
{
    __shared__ float As[16][68];
    __shared__ float Bs[16][68];
    const int tid = threadIdx.x;
    const int tx = tid & 15, ty = tid >> 4;
    const int col0 = blockIdx.x * 64, row0 = blockIdx.y * 64;
    const bool trans = (blockIdx.z == 1);
    const float* B = trans ? Wx : Wr;
    float* out = trans ? outRx : outWresp;

    float acc[4][4];
    #pragma unroll
    for (int i = 0; i < 4; i++)
        #pragma unroll
        for (int j = 0; j < 4; j++) acc[i][j] = 0.0f;

    for (int kt = 0; kt < 32; kt++) {
        const int k0 = kt * 16;
        {
            const int r = tid >> 2, k4 = (tid & 3) * 4;
            const float4 v = *(const float4*)&A[(size_t)(row0 + r) * Hh + k0 + k4];
            As[k4 + 0][r] = v.x; As[k4 + 1][r] = v.y;
            As[k4 + 2][r] = v.z; As[k4 + 3][r] = v.w;
        }
        if (trans) {
            const int c = tid >> 2, k4 = (tid & 3) * 4;
            const float4 v = *(const float4*)&B[(size_t)(col0 + c) * Hh + k0 + k4];
            Bs[k4 + 0][c] = v.x; Bs[k4 + 1][c] = v.y;
            Bs[k4 + 2][c] = v.z; Bs[k4 + 3][c] = v.w;
        } else {
            const int k = tid >> 4, c4 = (tid & 15) * 4;
            *(float4*)&Bs[k][c4] = *(const float4*)&B[(size_t)(k0 + k) * Hh + col0 + c4];
        }
        __syncthreads();

        #pragma unroll
        for (int k = 0; k < 16; k++) {
            float a[4], bb[4];
            #pragma unroll
            for (int i = 0; i < 4; i++) a[i]  = As[k][ty * 4 + i];
            #pragma unroll
            for (int j = 0; j < 4; j++) bb[j] = Bs[k][tx * 4 + j];
            #pragma unroll
            for (int i = 0; i < 4; i++)
                #pragma unroll
                for (int j = 0; j < 4; j++)
                    acc[i][j] = fmaf(a[i], bb[j], acc[i][j]);
        }
        __syncthreads();
    }

    #pragma unroll
    for (int i = 0; i < 4; i++)
        #pragma unroll
        for (int j = 0; j < 4; j++)
            out[(size_t)(row0 + ty * 4 + i) * Hh + col0 + tx * 4 + j] = acc[i][j];
}

// ---------------------------------------------------------------------------
// Final small GEMM: out = tanh(A @ Wp^T + Cadd)
// ---------------------------------------------------------------------------
__global__ __launch_bounds__(256)
void gemm_final(const float* __restrict__ A,
                const float* __restrict__ B,
                const float* __restrict__ Cadd,
                float* __restrict__ out)
{
    __shared__ float As[16][68];
    __shared__ float Bs[16][68];
    const int tid = threadIdx.x;
    const int tx = tid & 15, ty = tid >> 4;
    const int col0 = blockIdx.x * 64, row0 = blockIdx.y * 64;

    float acc[4][4];
    #pragma unroll
    for (int i = 0; i < 4; i++)
        #pragma unroll
        for (int j = 0; j < 4; j++) acc[i][j] = 0.0f;

    for (int kt = 0; kt < 32; kt++) {
        const int k0 = kt * 16;
        {
            const int r = tid >> 2, k4 = (tid & 3) * 4;
            const float4 v = *(const float4*)&A[(size_t)(row0 + r) * Hh + k0 + k4];
            As[k4 + 0][r] = v.x; As[k4 + 1][r] = v.y;
            As[k4 + 2][r] = v.z; As[k4 + 3][r] = v.w;
        }
        {
            const int c = tid >> 2, k4 = (tid & 3) * 4;
            const float4 v = *(const float4*)&B[(size_t)(col0 + c) * Hh + k0 + k4];
            Bs[k4 + 0][c] = v.x; Bs[k4 + 1][c] = v.y;
            Bs[k4 + 2][c] = v.z; Bs[k4 + 3][c] = v.w;
        }
        __syncthreads();

        #pragma unroll
        for (int k = 0; k < 16; k++) {
            float a[4], bb[4];
            #pragma unroll
            for (int i = 0; i < 4; i++) a[i]  = As[k][ty * 4 + i];
            #pragma unroll
            for (int j = 0; j < 4; j++) bb[j] = Bs[k][tx * 4 + j];
            #pragma unroll
            for (int i = 0; i < 4; i++)
                #pragma unroll
                for (int j = 0; j < 4; j++)
                    acc[i][j] = fmaf(a[i], bb[j], acc[i][j]);
        }
        __syncthreads();
    }

    #pragma unroll
    for (int i = 0; i < 4; i++)
        #pragma unroll
        for (int j = 0; j < 4; j++) {
            const size_t idx = (size_t)(row0 + ty * 4 + i) * Hh + col0 + tx * 4 + j;
            out[idx] = tanhf(acc[i][j] + Cadd[idx]);
        }
}

// ---------------------------------------------------------------------------
extern "C" void kernel_launch(void* const* d_in, const int* in_sizes, int n_in,
                              void* d_out, int out_size)
{
    const float* spk  = (const float*)d_in[0];
    const float* mask = (const float*)d_in[1];
    const float* tr   = (const float*)d_in[2];
    const float* Ws   = (const float*)d_in[3];
    const float* Wr   = (const float*)d_in[4];
    const float* w    = (const float*)d_in[5];
    const float* Wp   = (const float*)d_in[6];
    const float* Wx   = (const float*)d_in[7];

    float* out = (float*)d_out;
    float* resp_out  = out;
    float* alpha_out = out + Bsz * Hh;

    float *pWresp, *prx, *pspart, *presps;
    __nv_bfloat16 *pAhi, *pAlo, *pBhi, *pBlo;
    cudaGetSymbolAddress((void**)&pWresp, g_Wresp);
    cudaGetSymbolAddress((void**)&prx, g_rx);
    cudaGetSymbolAddress((void**)&pspart, g_scores_part);
    cudaGetSymbolAddress((void**)&presps, g_resps);
    cudaGetSymbolAddress((void**)&pAhi, g_Ahi);
    cudaGetSymbolAddress((void**)&pAlo, g_Alo);
    cudaGetSymbolAddress((void**)&pBhi, g_Bhi);
    cudaGetSymbolAddress((void**)&pBlo, g_Blo);

    static bool attr_set = false;
    if (!attr_set) {
        cudaFuncSetAttribute(score_mma,
                             cudaFuncAttributeMaxDynamicSharedMemorySize,
                             SM_BYTES);
        attr_set = true;
    }

    split_spk<<<(Bsz * Nn * Hh / 2) / 256, 256>>>(spk, pAhi, pAlo);
    split_ws<<<Hh / 2, Hh>>>(Ws, pBhi, pBlo);
    gemm_dual<<<dim3(8, 8, 2), 256>>>(tr, Wr, Wx, pWresp, prx);
    score_mma<<<dim3(4, 1024), 256, SM_BYTES>>>(pAhi, pAlo, pBhi, pBlo,
                                                pWresp, w, pspart);
    softmax_weight_kernel<<<Bsz, 512>>>(pspart, mask, spk, alpha_out, presps);
    gemm_final<<<dim3(8, 8), 256>>>(presps, Wp, prx, resp_out);
}

// round 9
// speedup vs baseline: 1.8774x; 1.0491x over previous
#include <cuda_runtime.h>
#include <cuda_bf16.h>
#include <cstdint>

// ---------------------------------------------------------------------------
// Spk_Attention: B=512, N=256, H=512. sm_103 plain target -> mma.sync bf16
// m16n8k16 3xBF16, hi/lo planes, ldmatrix.x4 + XOR swizzle, 3-stage k32
// pipeline, single sync per tile.  R9: latency-optimized small kernels.
// ---------------------------------------------------------------------------

#define Bsz 512
#define Nn  256
#define Hh  512

__device__ float g_Wresp[Bsz * Hh];
__device__ float g_rx[Bsz * Hh];
__device__ float g_scores_part[4 * Bsz * Nn];
__device__ float g_resps[Bsz * Hh];
__device__ __nv_bfloat16 g_Ahi[(size_t)Bsz * Nn * Hh];
__device__ __nv_bfloat16 g_Alo[(size_t)Bsz * Nn * Hh];
__device__ __nv_bfloat16 g_Bhi[Hh * Hh];
__device__ __nv_bfloat16 g_Blo[Hh * Hh];

// ---------------- helpers --------------------------------------------------
__device__ __forceinline__ float tanh_fast(float x) {
    float y;
    asm("tanh.approx.f32 %0, %1;" : "=f"(y) : "f"(x));
    return y;
}
__device__ __forceinline__ uint32_t smem_u32(const void* p) {
    uint32_t a;
    asm("{ .reg .u64 t; cvta.to.shared.u64 t, %1; cvt.u32.u64 %0, t; }"
        : "=r"(a) : "l"(p));
    return a;
}
__device__ __forceinline__ void cp16(uint32_t dst, const void* src) {
    asm volatile("cp.async.cg.shared.global [%0], [%1], 16;"
                 :: "r"(dst), "l"(src) : "memory");
}
__device__ __forceinline__ void ldsm4(uint32_t* r, uint32_t addr) {
    asm volatile("ldmatrix.sync.aligned.m8n8.x4.shared.b16 {%0,%1,%2,%3}, [%4];"
                 : "=r"(r[0]), "=r"(r[1]), "=r"(r[2]), "=r"(r[3]) : "r"(addr));
}
__device__ __forceinline__ void mma_bf16(float* d, const uint32_t* a,
                                         uint32_t b0, uint32_t b1) {
    asm volatile(
        "mma.sync.aligned.m16n8k16.row.col.f32.bf16.bf16.f32 "
        "{%0,%1,%2,%3}, {%4,%5,%6,%7}, {%8,%9}, {%0,%1,%2,%3};"
        : "+f"(d[0]), "+f"(d[1]), "+f"(d[2]), "+f"(d[3])
        : "r"(a[0]), "r"(a[1]), "r"(a[2]), "r"(a[3]), "r"(b0), "r"(b1));
}
__device__ __forceinline__ void split1(float v, __nv_bfloat16& h,
                                       __nv_bfloat16& l) {
    h = __float2bfloat16(v);
    l = __float2bfloat16(v - __bfloat162float(h));
}
__device__ __forceinline__ uint32_t swz(uint32_t r, uint32_t c) {
    return r * 64u + ((c ^ ((r >> 1) & 3u)) << 4);
}

// ---------------------------------------------------------------------------
// pre-split kernels
// ---------------------------------------------------------------------------
__global__ __launch_bounds__(256)
void split_spk(const float* __restrict__ A,
               __nv_bfloat16* __restrict__ Ahi,
               __nv_bfloat16* __restrict__ Alo) {
    const size_t j = (size_t)blockIdx.x * 256 + threadIdx.x;  // float4 index
    const float4 v = ((const float4*)A)[j];
    __nv_bfloat162 h0, l0, h1, l1;
    split1(v.x, h0.x, l0.x);
    split1(v.y, h0.y, l0.y);
    split1(v.z, h1.x, l1.x);
    split1(v.w, h1.y, l1.y);
    uint2 hp, lp;
    hp.x = *(uint32_t*)&h0; hp.y = *(uint32_t*)&h1;
    lp.x = *(uint32_t*)&l0; lp.y = *(uint32_t*)&l1;
    ((uint2*)Ahi)[j] = hp;
    ((uint2*)Alo)[j] = lp;
}

__global__ __launch_bounds__(512)
void split_ws(const float* __restrict__ Ws,
              __nv_bfloat16* __restrict__ Bhi,
              __nv_bfloat16* __restrict__ Blo) {
    const int p = blockIdx.x;
    const int n = threadIdx.x;
    __nv_bfloat162 h2, l2;
    split1(Ws[(2 * p) * Hh + n],     h2.x, l2.x);
    split1(Ws[(2 * p + 1) * Hh + n], h2.y, l2.y);
    ((__nv_bfloat162*)Bhi)[(size_t)n * (Hh / 2) + p] = h2;
    ((__nv_bfloat162*)Blo)[(size_t)n * (Hh / 2) + p] = l2;
}

// ---------------------------------------------------------------------------
// score kernel (UNCHANGED from R8): CTA 128x128, K512, 3-stage k32,
// XOR swizzle, single sync per tile, grid (4 col-chunks, 1024 row-blocks).
// ---------------------------------------------------------------------------
#define PLANE_W 2048u
#define STG_W   (4u * PLANE_W)
#define NSTG    3
#define SM_W    (NSTG * STG_W + 512)
#define SM_BYTES (SM_W * 4)

__global__ __launch_bounds__(256, 2)
void score_mma(const __nv_bfloat16* __restrict__ Ahi,
               const __nv_bfloat16* __restrict__ Alo,
               const __nv_bfloat16* __restrict__ Bhi,
               const __nv_bfloat16* __restrict__ Blo,
               const float* __restrict__ Wresp,
               const float* __restrict__ wvec,
               float* __restrict__ scores_part)
{
    extern __shared__ uint32_t smw[];
    float* WRs = (float*)(smw + NSTG * STG_W);
    float* WVs = WRs + 128;
    float* sp2 = WVs + 128;

    const int tid  = threadIdx.x;
    const int lane = tid & 31, wid = tid >> 5;
    const int wm = wid & 3, wn = wid >> 2;
    const int g  = lane >> 2, tg = lane & 3;
    const int col0 = blockIdx.x * 128;
    const int row0 = blockIdx.y * 128;
    const int b    = row0 >> 8;

    if (tid < 128) {
        WRs[tid] = Wresp[b * Hh + col0 + tid];
        WVs[tid] = wvec[col0 + tid];
    }

    const uint32_t sbase = smem_u32(smw);

    const uint32_t a_row = (lane & 7) | (((lane >> 3) & 1) << 3);
    const uint32_t a_chk = (lane >> 4) & 1;
    const uint32_t b_row = (lane & 7) | (((lane >> 4) & 1) << 3);
    const uint32_t b_chk = (lane >> 3) & 1;

    auto load_stage = [&](int kk, int slot) {
        const uint32_t db = sbase + (uint32_t)slot * (STG_W * 4);
        #pragma unroll
        for (int i = 0; i < 8; i++) {
            const int idx = tid + 256 * i;
            const int plane = idx >> 9;
            const uint32_t r = (idx >> 2) & 127;
            const uint32_t c = idx & 3;
            const __nv_bfloat16* src;
            if (plane == 0)
                src = Ahi + (size_t)(row0 + r) * Hh + kk * 32 + c * 8;
            else if (plane == 1)
                src = Alo + (size_t)(row0 + r) * Hh + kk * 32 + c * 8;
            else if (plane == 2)
                src = Bhi + (size_t)(col0 + r) * Hh + kk * 32 + c * 8;
            else
                src = Blo + (size_t)(col0 + r) * Hh + kk * 32 + c * 8;
            cp16(db + plane * (PLANE_W * 4) + swz(r, c), src);
        }
        asm volatile("cp.async.commit_group;" ::: "memory");
    };

    load_stage(0, 0);
    load_stage(1, 1);

    float acc[2][8][4];
    #pragma unroll
    for (int mt = 0; mt < 2; mt++)
        #pragma unroll
        for (int nt = 0; nt < 8; nt++)
            #pragma unroll
            for (int c = 0; c < 4; c++) acc[mt][nt][c] = 0.0f;

    #pragma unroll 1
    for (int kk = 0; kk < 16; kk++) {
        if (kk < 15) asm volatile("cp.async.wait_group 1;" ::: "memory");
        else         asm volatile("cp.async.wait_group 0;" ::: "memory");
        __syncthreads();

        if (kk + 2 < 16) load_stage(kk + 2, (kk + 2) % 3);

        const uint32_t stg  = sbase + (uint32_t)(kk % 3) * (STG_W * 4);
        const uint32_t pAhi = stg;
        const uint32_t pAlo = stg + PLANE_W * 4;
        const uint32_t pBhi = stg + 2 * PLANE_W * 4;
        const uint32_t pBlo = stg + 3 * PLANE_W * 4;

        #pragma unroll
        for (int ks = 0; ks < 2; ks++) {
            uint32_t ahi[2][4], alo[2][4];
            #pragma unroll
            for (int mt = 0; mt < 2; mt++) {
                const uint32_t r = wm * 32 + mt * 16 + a_row;
                const uint32_t off = swz(r, ks * 2 + a_chk);
                ldsm4(ahi[mt], pAhi + off);
                ldsm4(alo[mt], pAlo + off);
            }
            #pragma unroll
            for (int ntp = 0; ntp < 4; ntp++) {
                const uint32_t r = wn * 64 + ntp * 16 + b_row;
                const uint32_t off = swz(r, ks * 2 + b_chk);
                uint32_t bh[4], bl[4];
                ldsm4(bh, pBhi + off);
                ldsm4(bl, pBlo + off);
                #pragma unroll
                for (int half = 0; half < 2; half++) {
                    const int nt = ntp * 2 + half;
                    const uint32_t b0h = bh[half * 2], b1h = bh[half * 2 + 1];
                    const uint32_t b0l = bl[half * 2], b1l = bl[half * 2 + 1];
                    #pragma unroll
                    for (int mt = 0; mt < 2; mt++) {
                        mma_bf16(acc[mt][nt], ahi[mt], b0l, b1l);
                        mma_bf16(acc[mt][nt], alo[mt], b0h, b1h);
                        mma_bf16(acc[mt][nt], ahi[mt], b0h, b1h);
                    }
                }
            }
        }
    }

    #pragma unroll
    for (int mt = 0; mt < 2; mt++) {
        float plo = 0.0f, phi = 0.0f;
        #pragma unroll
        for (int nt = 0; nt < 8; nt++) {
            const int c0 = wn * 64 + nt * 8 + 2 * tg;
            const int c1 = c0 + 1;
            plo += tanh_fast(acc[mt][nt][0] + WRs[c0]) * WVs[c0]
                 + tanh_fast(acc[mt][nt][1] + WRs[c1]) * WVs[c1];
            phi += tanh_fast(acc[mt][nt][2] + WRs[c0]) * WVs[c0]
                 + tanh_fast(acc[mt][nt][3] + WRs[c1]) * WVs[c1];
        }
        plo += __shfl_xor_sync(0xFFFFFFFFu, plo, 1);
        plo += __shfl_xor_sync(0xFFFFFFFFu, plo, 2);
        phi += __shfl_xor_sync(0xFFFFFFFFu, phi, 1);
        phi += __shfl_xor_sync(0xFFFFFFFFu, phi, 2);
        if (tg == 0) {
            sp2[wn * 128 + wm * 32 + mt * 16 + g]     = plo;
            sp2[wn * 128 + wm * 32 + mt * 16 + 8 + g] = phi;
        }
    }
    __syncthreads();
    if (tid < 128)
        scores_part[(size_t)blockIdx.x * (Bsz * Nn) + row0 + tid] =
            sp2[tid] + sp2[128 + tid];
}

// ---------------------------------------------------------------------------
// Per-batch softmax + resp_s = alpha . spk_emb  (8-way ILP)
// ---------------------------------------------------------------------------
__global__ __launch_bounds__(512)
void softmax_weight_kernel(const float* __restrict__ scores_part,
                           const float* __restrict__ mask,
                           const float* __restrict__ emb,
                           float* __restrict__ alpha_out,
                           float* __restrict__ resps)
{
    const int b = blockIdx.x;
    const int tid = threadIdx.x;
    __shared__ float sa[256];
    __shared__ float red[512];

    float t = -1e30f;
    if (tid < Nn) {
        const size_t i = (size_t)b * Nn + tid;
        float s = scores_part[i];
        s += scores_part[(size_t)(Bsz * Nn) + i];
        s += scores_part[(size_t)(2 * Bsz * Nn) + i];
        s += scores_part[(size_t)(3 * Bsz * Nn) + i];
        t = s * mask[i];
    }

    red[tid] = t; __syncthreads();
    #pragma unroll
    for (int s = 256; s > 0; s >>= 1) {
        if (tid < s) red[tid] = fmaxf(red[tid], red[tid + s]);
        __syncthreads();
    }
    const float m = red[0];
    __syncthreads();

    const float e = (tid < Nn) ? __expf(t - m) : 0.0f;
    red[tid] = e; __syncthreads();
    #pragma unroll
    for (int s = 256; s > 0; s >>= 1) {
        if (tid < s) red[tid] += red[tid + s];
        __syncthreads();
    }
    const float a = e / red[0];

    if (tid < Nn) {
        alpha_out[(size_t)b * Nn + tid] = a;
        sa[tid] = a;
    }
    __syncthreads();

    const float* eb = emb + (size_t)b * Nn * Hh + tid;
    float c0 = 0.f, c1 = 0.f, c2 = 0.f, c3 = 0.f;
    float c4 = 0.f, c5 = 0.f, c6 = 0.f, c7 = 0.f;
    #pragma unroll 1
    for (int n = 0; n < Nn; n += 8) {
        c0 = fmaf(sa[n    ], eb[(size_t)(n    ) * Hh], c0);
        c1 = fmaf(sa[n + 1], eb[(size_t)(n + 1) * Hh], c1);
        c2 = fmaf(sa[n + 2], eb[(size_t)(n + 2) * Hh], c2);
        c3 = fmaf(sa[n + 3], eb[(size_t)(n + 3) * Hh], c3);
        c4 = fmaf(sa[n + 4], eb[(size_t)(n + 4) * Hh], c4);
        c5 = fmaf(sa[n + 5], eb[(size_t)(n + 5) * Hh], c5);
        c6 = fmaf(sa[n + 6], eb[(size_t)(n + 6) * Hh], c6);
        c7 = fmaf(sa[n + 7], eb[(size_t)(n + 7) * Hh], c7);
    }
    resps[b * Hh + tid] = ((c0 + c1) + (c2 + c3)) + ((c4 + c5) + (c6 + c7));
}

// ---------------------------------------------------------------------------
// Small GEMM, latency-optimized: 32 rows x 64 cols per CTA, 256 threads,
// microtile 2x4.  out = act(A @ op(B) [+ Cadd])
// ---------------------------------------------------------------------------
template <bool TRANSB, bool DOADD, bool DOTANH>
__device__ __forceinline__
void gemm_body(const float* __restrict__ A,
               const float* __restrict__ B,
               const float* __restrict__ Cadd,
               float* __restrict__ out,
               int row0, int col0)
{
    __shared__ float As[16][36];
    __shared__ float Bs[16][68];
    const int tid = threadIdx.x;
    const int tx = tid & 15, ty = tid >> 4;   // 16 x 16

    float acc[2][4];
    #pragma unroll
    for (int i = 0; i < 2; i++)
        #pragma unroll
        for (int j = 0; j < 4; j++) acc[i][j] = 0.0f;

    for (int kt = 0; kt < 32; kt++) {
        const int k0 = kt * 16;
        if (tid < 128) {   // A: 32 rows x 16 k
            const int r = tid >> 2, k4 = (tid & 3) * 4;
            const float4 v = *(const float4*)&A[(size_t)(row0 + r) * Hh + k0 + k4];
            As[k4 + 0][r] = v.x; As[k4 + 1][r] = v.y;
            As[k4 + 2][r] = v.z; As[k4 + 3][r] = v.w;
        }
        if (TRANSB) {      // B: 64 c-rows x 16 k
            const int c = tid >> 2, k4 = (tid & 3) * 4;
            const float4 v = *(const float4*)&B[(size_t)(col0 + c) * Hh + k0 + k4];
            Bs[k4 + 0][c] = v.x; Bs[k4 + 1][c] = v.y;
            Bs[k4 + 2][c] = v.z; Bs[k4 + 3][c] = v.w;
        } else {           // B: 16 k x 64 cols
            const int k = tid >> 4, c4 = (tid & 15) * 4;
            *(float4*)&Bs[k][c4] = *(const float4*)&B[(size_t)(k0 + k) * Hh + col0 + c4];
        }
        __syncthreads();

        #pragma unroll
        for (int k = 0; k < 16; k++) {
            float a0 = As[k][ty * 2], a1 = As[k][ty * 2 + 1];
            float bb[4];
            #pragma unroll
            for (int j = 0; j < 4; j++) bb[j] = Bs[k][tx * 4 + j];
            #pragma unroll
            for (int j = 0; j < 4; j++) {
                acc[0][j] = fmaf(a0, bb[j], acc[0][j]);
                acc[1][j] = fmaf(a1, bb[j], acc[1][j]);
            }
        }
        __syncthreads();
    }

    #pragma unroll
    for (int i = 0; i < 2; i++)
        #pragma unroll
        for (int j = 0; j < 4; j++) {
            const size_t idx = (size_t)(row0 + ty * 2 + i) * Hh + col0 + tx * 4 + j;
            float v = acc[i][j];
            if (DOADD) v += Cadd[idx];
            if (DOTANH) v = tanhf(v);
            out[idx] = v;
        }
}

// dual: z=0 -> Wresp = tr @ Wr (no trans) ; z=1 -> rx = tr @ Wx^T (trans)
__global__ __launch_bounds__(256)
void gemm_dual(const float* __restrict__ A,
               const float* __restrict__ Wr,
               const float* __restrict__ Wx,
               float* __restrict__ outWresp,
               float* __restrict__ outRx)
{
    const int row0 = blockIdx.y * 32, col0 = blockIdx.x * 64;
    if (blockIdx.z == 0)
        gemm_body<false, false, false>(A, Wr, nullptr, outWresp, row0, col0);
    else
        gemm_body<true, false, false>(A, Wx, nullptr, outRx, row0, col0);
}

__global__ __launch_bounds__(256)
void gemm_final(const float* __restrict__ A,
                const float* __restrict__ B,
                const float* __restrict__ Cadd,
                float* __restrict__ out)
{
    gemm_body<true, true, true>(A, B, Cadd, out, blockIdx.y * 32, blockIdx.x * 64);
}

// ---------------------------------------------------------------------------
extern "C" void kernel_launch(void* const* d_in, const int* in_sizes, int n_in,
                              void* d_out, int out_size)
{
    const float* spk  = (const float*)d_in[0];
    const float* mask = (const float*)d_in[1];
    const float* tr   = (const float*)d_in[2];
    const float* Ws   = (const float*)d_in[3];
    const float* Wr   = (const float*)d_in[4];
    const float* w    = (const float*)d_in[5];
    const float* Wp   = (const float*)d_in[6];
    const float* Wx   = (const float*)d_in[7];

    float* out = (float*)d_out;
    float* resp_out  = out;
    float* alpha_out = out + Bsz * Hh;

    float *pWresp, *prx, *pspart, *presps;
    __nv_bfloat16 *pAhi, *pAlo, *pBhi, *pBlo;
    cudaGetSymbolAddress((void**)&pWresp, g_Wresp);
    cudaGetSymbolAddress((void**)&prx, g_rx);
    cudaGetSymbolAddress((void**)&pspart, g_scores_part);
    cudaGetSymbolAddress((void**)&presps, g_resps);
    cudaGetSymbolAddress((void**)&pAhi, g_Ahi);
    cudaGetSymbolAddress((void**)&pAlo, g_Alo);
    cudaGetSymbolAddress((void**)&pBhi, g_Bhi);
    cudaGetSymbolAddress((void**)&pBlo, g_Blo);

    static bool attr_set = false;
    if (!attr_set) {
        cudaFuncSetAttribute(score_mma,
                             cudaFuncAttributeMaxDynamicSharedMemorySize,
                             SM_BYTES);
        attr_set = true;
    }

    split_spk<<<(Bsz * Nn * Hh / 4) / 256, 256>>>(spk, pAhi, pAlo);
    split_ws<<<Hh / 2, Hh>>>(Ws, pBhi, pBlo);
    gemm_dual<<<dim3(8, 16, 2), 256>>>(tr, Wr, Wx, pWresp, prx);
    score_mma<<<dim3(4, 1024), 256, SM_BYTES>>>(pAhi, pAlo, pBhi, pBlo,
                                                pWresp, w, pspart);
    softmax_weight_kernel<<<Bsz, 512>>>(pspart, mask, spk, alpha_out, presps);
    gemm_final<<<dim3(8, 16), 256>>>(presps, Wp, prx, resp_out);
}

// round 10
// speedup vs baseline: 1.9842x; 1.0569x over previous
#include <cuda_runtime.h>
#include <cuda_bf16.h>
#include <cstdint>

// ---------------------------------------------------------------------------
// Spk_Attention: B=512, N=256, H=512. sm_103 plain target -> mma.sync bf16
// m16n8k16 3xBF16, hi/lo planes, ldmatrix.x4 + XOR swizzle, 3-stage k32
// pipeline.  R10: fused prep launch (splits + dual GEMM), 2-way softmax split.
// ---------------------------------------------------------------------------

#define Bsz 512
#define Nn  256
#define Hh  512

__device__ float g_Wresp[Bsz * Hh];
__device__ float g_rx[Bsz * Hh];
__device__ float g_scores_part[4 * Bsz * Nn];
__device__ float g_resps[Bsz * Hh];
__device__ __nv_bfloat16 g_Ahi[(size_t)Bsz * Nn * Hh];
__device__ __nv_bfloat16 g_Alo[(size_t)Bsz * Nn * Hh];
__device__ __nv_bfloat16 g_Bhi[Hh * Hh];
__device__ __nv_bfloat16 g_Blo[Hh * Hh];

// ---------------- helpers --------------------------------------------------
__device__ __forceinline__ float tanh_fast(float x) {
    float y;
    asm("tanh.approx.f32 %0, %1;" : "=f"(y) : "f"(x));
    return y;
}
__device__ __forceinline__ uint32_t smem_u32(const void* p) {
    uint32_t a;
    asm("{ .reg .u64 t; cvta.to.shared.u64 t, %1; cvt.u32.u64 %0, t; }"
        : "=r"(a) : "l"(p));
    return a;
}
__device__ __forceinline__ void cp16(uint32_t dst, const void* src) {
    asm volatile("cp.async.cg.shared.global [%0], [%1], 16;"
                 :: "r"(dst), "l"(src) : "memory");
}
__device__ __forceinline__ void ldsm4(uint32_t* r, uint32_t addr) {
    asm volatile("ldmatrix.sync.aligned.m8n8.x4.shared.b16 {%0,%1,%2,%3}, [%4];"
                 : "=r"(r[0]), "=r"(r[1]), "=r"(r[2]), "=r"(r[3]) : "r"(addr));
}
__device__ __forceinline__ void mma_bf16(float* d, const uint32_t* a,
                                         uint32_t b0, uint32_t b1) {
    asm volatile(
        "mma.sync.aligned.m16n8k16.row.col.f32.bf16.bf16.f32 "
        "{%0,%1,%2,%3}, {%4,%5,%6,%7}, {%8,%9}, {%0,%1,%2,%3};"
        : "+f"(d[0]), "+f"(d[1]), "+f"(d[2]), "+f"(d[3])
        : "r"(a[0]), "r"(a[1]), "r"(a[2]), "r"(a[3]), "r"(b0), "r"(b1));
}
__device__ __forceinline__ void split1(float v, __nv_bfloat16& h,
                                       __nv_bfloat16& l) {
    h = __float2bfloat16(v);
    l = __float2bfloat16(v - __bfloat162float(h));
}
__device__ __forceinline__ uint32_t swz(uint32_t r, uint32_t c) {
    return r * 64u + ((c ^ ((r >> 1) & 3u)) << 4);
}

// ---------------------------------------------------------------------------
// Small GEMM body: 32 rows x 64 cols per CTA, 256 threads, microtile 2x4.
// ---------------------------------------------------------------------------
template <bool TRANSB, bool DOADD, bool DOTANH>
__device__ __forceinline__
void gemm_body(const float* __restrict__ A,
               const float* __restrict__ B,
               const float* __restrict__ Cadd,
               float* __restrict__ out,
               int row0, int col0)
{
    __shared__ float As[16][36];
    __shared__ float Bs[16][68];
    const int tid = threadIdx.x;
    const int tx = tid & 15, ty = tid >> 4;

    float acc[2][4];
    #pragma unroll
    for (int i = 0; i < 2; i++)
        #pragma unroll
        for (int j = 0; j < 4; j++) acc[i][j] = 0.0f;

    for (int kt = 0; kt < 32; kt++) {
        const int k0 = kt * 16;
        if (tid < 128) {
            const int r = tid >> 2, k4 = (tid & 3) * 4;
            const float4 v = *(const float4*)&A[(size_t)(row0 + r) * Hh + k0 + k4];
            As[k4 + 0][r] = v.x; As[k4 + 1][r] = v.y;
            As[k4 + 2][r] = v.z; As[k4 + 3][r] = v.w;
        }
        if (TRANSB) {
            const int c = tid >> 2, k4 = (tid & 3) * 4;
            const float4 v = *(const float4*)&B[(size_t)(col0 + c) * Hh + k0 + k4];
            Bs[k4 + 0][c] = v.x; Bs[k4 + 1][c] = v.y;
            Bs[k4 + 2][c] = v.z; Bs[k4 + 3][c] = v.w;
        } else {
            const int k = tid >> 4, c4 = (tid & 15) * 4;
            *(float4*)&Bs[k][c4] = *(const float4*)&B[(size_t)(k0 + k) * Hh + col0 + c4];
        }
        __syncthreads();

        #pragma unroll
        for (int k = 0; k < 16; k++) {
            float a0 = As[k][ty * 2], a1 = As[k][ty * 2 + 1];
            float bb[4];
            #pragma unroll
            for (int j = 0; j < 4; j++) bb[j] = Bs[k][tx * 4 + j];
            #pragma unroll
            for (int j = 0; j < 4; j++) {
                acc[0][j] = fmaf(a0, bb[j], acc[0][j]);
                acc[1][j] = fmaf(a1, bb[j], acc[1][j]);
            }
        }
        __syncthreads();
    }

    #pragma unroll
    for (int i = 0; i < 2; i++)
        #pragma unroll
        for (int j = 0; j < 4; j++) {
            const size_t idx = (size_t)(row0 + ty * 2 + i) * Hh + col0 + tx * 4 + j;
            float v = acc[i][j];
            if (DOADD) v += Cadd[idx];
            if (DOTANH) v = tanhf(v);
            out[idx] = v;
        }
}

// ---------------------------------------------------------------------------
// Fused prep: blockIdx.x partition
//   [0,256)    gemm_dual  (z = bx>>7: 0 -> Wresp = tr@Wr, 1 -> rx = tr@Wx^T)
//   [256,384)  split_ws   (128 CTAs x 256 thr x 4 jobs = 131072 (n,p) pairs)
//   [384,2432) split_spk  (2048 CTAs x 256 thr x 32 float4 = 16.7M float4)
// ---------------------------------------------------------------------------
__global__ __launch_bounds__(256)
void prep_fused(const float* __restrict__ spk,
                const float* __restrict__ Ws,
                const float* __restrict__ tr,
                const float* __restrict__ Wr,
                const float* __restrict__ Wx,
                __nv_bfloat16* __restrict__ Ahi,
                __nv_bfloat16* __restrict__ Alo,
                __nv_bfloat16* __restrict__ Bhi,
                __nv_bfloat16* __restrict__ Blo,
                float* __restrict__ outWresp,
                float* __restrict__ outRx)
{
    const int bx = blockIdx.x;
    if (bx < 256) {
        const int z = bx >> 7, rem = bx & 127;
        const int col0 = (rem & 7) * 64, row0 = (rem >> 3) * 32;
        if (z == 0)
            gemm_body<false, false, false>(tr, Wr, nullptr, outWresp, row0, col0);
        else
            gemm_body<true, false, false>(tr, Wx, nullptr, outRx, row0, col0);
    } else if (bx < 384) {
        const int base = (bx - 256) * 1024 + threadIdx.x * 4;
        #pragma unroll
        for (int i = 0; i < 4; i++) {
            const int j = base + i;
            const int n = j >> 8, p = j & 255;
            __nv_bfloat162 h2, l2;
            split1(Ws[(2 * p) * Hh + n],     h2.x, l2.x);
            split1(Ws[(2 * p + 1) * Hh + n], h2.y, l2.y);
            ((__nv_bfloat162*)Bhi)[(size_t)n * (Hh / 2) + p] = h2;
            ((__nv_bfloat162*)Blo)[(size_t)n * (Hh / 2) + p] = l2;
        }
    } else {
        const size_t t = (size_t)(bx - 384) * 256 + threadIdx.x;  // 0..524287
        const float4* src = (const float4*)spk;
        #pragma unroll 4
        for (int i = 0; i < 32; i++) {
            const size_t j = t + (size_t)i * 524288;
            const float4 v = src[j];
            __nv_bfloat162 h0, l0, h1, l1;
            split1(v.x, h0.x, l0.x);
            split1(v.y, h0.y, l0.y);
            split1(v.z, h1.x, l1.x);
            split1(v.w, h1.y, l1.y);
            uint2 hp, lp;
            hp.x = *(uint32_t*)&h0; hp.y = *(uint32_t*)&h1;
            lp.x = *(uint32_t*)&l0; lp.y = *(uint32_t*)&l1;
            ((uint2*)Ahi)[j] = hp;
            ((uint2*)Alo)[j] = lp;
        }
    }
}

// ---------------------------------------------------------------------------
// score kernel (UNCHANGED from R8/R9): CTA 128x128, K512, 3-stage k32,
// XOR swizzle, single sync per tile, grid (4 col-chunks, 1024 row-blocks).
// ---------------------------------------------------------------------------
#define PLANE_W 2048u
#define STG_W   (4u * PLANE_W)
#define NSTG    3
#define SM_W    (NSTG * STG_W + 512)
#define SM_BYTES (SM_W * 4)

__global__ __launch_bounds__(256, 2)
void score_mma(const __nv_bfloat16* __restrict__ Ahi,
               const __nv_bfloat16* __restrict__ Alo,
               const __nv_bfloat16* __restrict__ Bhi,
               const __nv_bfloat16* __restrict__ Blo,
               const float* __restrict__ Wresp,
               const float* __restrict__ wvec,
               float* __restrict__ scores_part)
{
    extern __shared__ uint32_t smw[];
    float* WRs = (float*)(smw + NSTG * STG_W);
    float* WVs = WRs + 128;
    float* sp2 = WVs + 128;

    const int tid  = threadIdx.x;
    const int lane = tid & 31, wid = tid >> 5;
    const int wm = wid & 3, wn = wid >> 2;
    const int g  = lane >> 2, tg = lane & 3;
    const int col0 = blockIdx.x * 128;
    const int row0 = blockIdx.y * 128;
    const int b    = row0 >> 8;

    if (tid < 128) {
        WRs[tid] = Wresp[b * Hh + col0 + tid];
        WVs[tid] = wvec[col0 + tid];
    }

    const uint32_t sbase = smem_u32(smw);

    const uint32_t a_row = (lane & 7) | (((lane >> 3) & 1) << 3);
    const uint32_t a_chk = (lane >> 4) & 1;
    const uint32_t b_row = (lane & 7) | (((lane >> 4) & 1) << 3);
    const uint32_t b_chk = (lane >> 3) & 1;

    auto load_stage = [&](int kk, int slot) {
        const uint32_t db = sbase + (uint32_t)slot * (STG_W * 4);
        #pragma unroll
        for (int i = 0; i < 8; i++) {
            const int idx = tid + 256 * i;
            const int plane = idx >> 9;
            const uint32_t r = (idx >> 2) & 127;
            const uint32_t c = idx & 3;
            const __nv_bfloat16* src;
            if (plane == 0)
                src = Ahi + (size_t)(row0 + r) * Hh + kk * 32 + c * 8;
            else if (plane == 1)
                src = Alo + (size_t)(row0 + r) * Hh + kk * 32 + c * 8;
            else if (plane == 2)
                src = Bhi + (size_t)(col0 + r) * Hh + kk * 32 + c * 8;
            else
                src = Blo + (size_t)(col0 + r) * Hh + kk * 32 + c * 8;
            cp16(db + plane * (PLANE_W * 4) + swz(r, c), src);
        }
        asm volatile("cp.async.commit_group;" ::: "memory");
    };

    load_stage(0, 0);
    load_stage(1, 1);

    float acc[2][8][4];
    #pragma unroll
    for (int mt = 0; mt < 2; mt++)
        #pragma unroll
        for (int nt = 0; nt < 8; nt++)
            #pragma unroll
            for (int c = 0; c < 4; c++) acc[mt][nt][c] = 0.0f;

    #pragma unroll 1
    for (int kk = 0; kk < 16; kk++) {
        if (kk < 15) asm volatile("cp.async.wait_group 1;" ::: "memory");
        else         asm volatile("cp.async.wait_group 0;" ::: "memory");
        __syncthreads();

        if (kk + 2 < 16) load_stage(kk + 2, (kk + 2) % 3);

        const uint32_t stg  = sbase + (uint32_t)(kk % 3) * (STG_W * 4);
        const uint32_t pAhi = stg;
        const uint32_t pAlo = stg + PLANE_W * 4;
        const uint32_t pBhi = stg + 2 * PLANE_W * 4;
        const uint32_t pBlo = stg + 3 * PLANE_W * 4;

        #pragma unroll
        for (int ks = 0; ks < 2; ks++) {
            uint32_t ahi[2][4], alo[2][4];
            #pragma unroll
            for (int mt = 0; mt < 2; mt++) {
                const uint32_t r = wm * 32 + mt * 16 + a_row;
                const uint32_t off = swz(r, ks * 2 + a_chk);
                ldsm4(ahi[mt], pAhi + off);
                ldsm4(alo[mt], pAlo + off);
            }
            #pragma unroll
            for (int ntp = 0; ntp < 4; ntp++) {
                const uint32_t r = wn * 64 + ntp * 16 + b_row;
                const uint32_t off = swz(r, ks * 2 + b_chk);
                uint32_t bh[4], bl[4];
                ldsm4(bh, pBhi + off);
                ldsm4(bl, pBlo + off);
                #pragma unroll
                for (int half = 0; half < 2; half++) {
                    const int nt = ntp * 2 + half;
                    const uint32_t b0h = bh[half * 2], b1h = bh[half * 2 + 1];
                    const uint32_t b0l = bl[half * 2], b1l = bl[half * 2 + 1];
                    #pragma unroll
                    for (int mt = 0; mt < 2; mt++) {
                        mma_bf16(acc[mt][nt], ahi[mt], b0l, b1l);
                        mma_bf16(acc[mt][nt], alo[mt], b0h, b1h);
                        mma_bf16(acc[mt][nt], ahi[mt], b0h, b1h);
                    }
                }
            }
        }
    }

    #pragma unroll
    for (int mt = 0; mt < 2; mt++) {
        float plo = 0.0f, phi = 0.0f;
        #pragma unroll
        for (int nt = 0; nt < 8; nt++) {
            const int c0 = wn * 64 + nt * 8 + 2 * tg;
            const int c1 = c0 + 1;
            plo += tanh_fast(acc[mt][nt][0] + WRs[c0]) * WVs[c0]
                 + tanh_fast(acc[mt][nt][1] + WRs[c1]) * WVs[c1];
            phi += tanh_fast(acc[mt][nt][2] + WRs[c0]) * WVs[c0]
                 + tanh_fast(acc[mt][nt][3] + WRs[c1]) * WVs[c1];
        }
        plo += __shfl_xor_sync(0xFFFFFFFFu, plo, 1);
        plo += __shfl_xor_sync(0xFFFFFFFFu, plo, 2);
        phi += __shfl_xor_sync(0xFFFFFFFFu, phi, 1);
        phi += __shfl_xor_sync(0xFFFFFFFFu, phi, 2);
        if (tg == 0) {
            sp2[wn * 128 + wm * 32 + mt * 16 + g]     = plo;
            sp2[wn * 128 + wm * 32 + mt * 16 + 8 + g] = phi;
        }
    }
    __syncthreads();
    if (tid < 128)
        scores_part[(size_t)blockIdx.x * (Bsz * Nn) + row0 + tid] =
            sp2[tid] + sp2[128 + tid];
}

// ---------------------------------------------------------------------------
// Per-batch softmax + resp_s, split over h halves: grid (512 b, 2 halves),
// 256 threads. Both halves recompute the cheap softmax; half 0 writes alpha.
// ---------------------------------------------------------------------------
__global__ __launch_bounds__(256)
void softmax_weight_kernel(const float* __restrict__ scores_part,
                           const float* __restrict__ mask,
                           const float* __restrict__ emb,
                           float* __restrict__ alpha_out,
                           float* __restrict__ resps)
{
    const int b = blockIdx.x;
    const int half = blockIdx.y;
    const int tid = threadIdx.x;     // 0..255 == n
    __shared__ float sa[256];
    __shared__ float red[256];

    const size_t i = (size_t)b * Nn + tid;
    float s = scores_part[i];
    s += scores_part[(size_t)(Bsz * Nn) + i];
    s += scores_part[(size_t)(2 * Bsz * Nn) + i];
    s += scores_part[(size_t)(3 * Bsz * Nn) + i];
    const float t = s * mask[i];

    red[tid] = t; __syncthreads();
    #pragma unroll
    for (int st = 128; st > 0; st >>= 1) {
        if (tid < st) red[tid] = fmaxf(red[tid], red[tid + st]);
        __syncthreads();
    }
    const float m = red[0];
    __syncthreads();

    const float e = __expf(t - m);
    red[tid] = e; __syncthreads();
    #pragma unroll
    for (int st = 128; st > 0; st >>= 1) {
        if (tid < st) red[tid] += red[tid + st];
        __syncthreads();
    }
    const float a = e / red[0];

    if (half == 0) alpha_out[i] = a;
    sa[tid] = a;
    __syncthreads();

    const int h = half * 256 + tid;
    const float* eb = emb + (size_t)b * Nn * Hh + h;
    float c0 = 0.f, c1 = 0.f, c2 = 0.f, c3 = 0.f;
    float c4 = 0.f, c5 = 0.f, c6 = 0.f, c7 = 0.f;
    #pragma unroll 1
    for (int n = 0; n < Nn; n += 8) {
        c0 = fmaf(sa[n    ], eb[(size_t)(n    ) * Hh], c0);
        c1 = fmaf(sa[n + 1], eb[(size_t)(n + 1) * Hh], c1);
        c2 = fmaf(sa[n + 2], eb[(size_t)(n + 2) * Hh], c2);
        c3 = fmaf(sa[n + 3], eb[(size_t)(n + 3) * Hh], c3);
        c4 = fmaf(sa[n + 4], eb[(size_t)(n + 4) * Hh], c4);
        c5 = fmaf(sa[n + 5], eb[(size_t)(n + 5) * Hh], c5);
        c6 = fmaf(sa[n + 6], eb[(size_t)(n + 6) * Hh], c6);
        c7 = fmaf(sa[n + 7], eb[(size_t)(n + 7) * Hh], c7);
    }
    resps[b * Hh + h] = ((c0 + c1) + (c2 + c3)) + ((c4 + c5) + (c6 + c7));
}

// ---------------------------------------------------------------------------
__global__ __launch_bounds__(256)
void gemm_final(const float* __restrict__ A,
                const float* __restrict__ B,
                const float* __restrict__ Cadd,
                float* __restrict__ out)
{
    gemm_body<true, true, true>(A, B, Cadd, out, blockIdx.y * 32, blockIdx.x * 64);
}

// ---------------------------------------------------------------------------
extern "C" void kernel_launch(void* const* d_in, const int* in_sizes, int n_in,
                              void* d_out, int out_size)
{
    const float* spk  = (const float*)d_in[0];
    const float* mask = (const float*)d_in[1];
    const float* tr   = (const float*)d_in[2];
    const float* Ws   = (const float*)d_in[3];
    const float* Wr   = (const float*)d_in[4];
    const float* w    = (const float*)d_in[5];
    const float* Wp   = (const float*)d_in[6];
    const float* Wx   = (const float*)d_in[7];

    float* out = (float*)d_out;
    float* resp_out  = out;
    float* alpha_out = out + Bsz * Hh;

    float *pWresp, *prx, *pspart, *presps;
    __nv_bfloat16 *pAhi, *pAlo, *pBhi, *pBlo;
    cudaGetSymbolAddress((void**)&pWresp, g_Wresp);
    cudaGetSymbolAddress((void**)&prx, g_rx);
    cudaGetSymbolAddress((void**)&pspart, g_scores_part);
    cudaGetSymbolAddress((void**)&presps, g_resps);
    cudaGetSymbolAddress((void**)&pAhi, g_Ahi);
    cudaGetSymbolAddress((void**)&pAlo, g_Alo);
    cudaGetSymbolAddress((void**)&pBhi, g_Bhi);
    cudaGetSymbolAddress((void**)&pBlo, g_Blo);

    static bool attr_set = false;
    if (!attr_set) {
        cudaFuncSetAttribute(score_mma,
                             cudaFuncAttributeMaxDynamicSharedMemorySize,
                             SM_BYTES);
        attr_set = true;
    }

    prep_fused<<<2432, 256>>>(spk, Ws, tr, Wr, Wx,
                              pAhi, pAlo, pBhi, pBlo, pWresp, prx);
    score_mma<<<dim3(4, 1024), 256, SM_BYTES>>>(pAhi, pAlo, pBhi, pBlo,
                                                pWresp, w, pspart);
    softmax_weight_kernel<<<dim3(512, 2), 256>>>(pspart, mask, spk,
                                                 alpha_out, presps);
    gemm_final<<<dim3(8, 16), 256>>>(presps, Wp, prx, resp_out);
}

// round 11
// speedup vs baseline: 2.0442x; 1.0302x over previous
#include <cuda_runtime.h>
#include <cuda_bf16.h>
#include <cstdint>

// ---------------------------------------------------------------------------
// Spk_Attention: B=512, N=256, H=512. sm_103 plain target -> mma.sync bf16
// m16n8k16 3xBF16.  R11: A-operand split fused INTO score_mma (fp32 staged,
// hi/lo built in registers) -- no more 512MB split_spk pass; split-K small
// GEMMs with deterministic combine.
// ---------------------------------------------------------------------------

#define Bsz 512
#define Nn  256
#define Hh  512
#define HB  (Hh * Hh)          // 262144

__device__ float g_scores_part[4 * Bsz * Nn];
__device__ float g_resps[Bsz * Hh];
__device__ float g_dual_part[8 * HB];   // [z(2)][kc(4)][512*512]
__device__ float g_fin_part[4 * HB];    // [kc(4)][512*512]
__device__ __nv_bfloat16 g_Bhi[HB];     // WsT hi plane [n][k]
__device__ __nv_bfloat16 g_Blo[HB];

// ---------------- helpers --------------------------------------------------
__device__ __forceinline__ float tanh_fast(float x) {
    float y;
    asm("tanh.approx.f32 %0, %1;" : "=f"(y) : "f"(x));
    return y;
}
__device__ __forceinline__ uint32_t smem_u32(const void* p) {
    uint32_t a;
    asm("{ .reg .u64 t; cvta.to.shared.u64 t, %1; cvt.u32.u64 %0, t; }"
        : "=r"(a) : "l"(p));
    return a;
}
__device__ __forceinline__ void cp16(uint32_t dst, const void* src) {
    asm volatile("cp.async.cg.shared.global [%0], [%1], 16;"
                 :: "r"(dst), "l"(src) : "memory");
}
__device__ __forceinline__ void ldsm4(uint32_t* r, uint32_t addr) {
    asm volatile("ldmatrix.sync.aligned.m8n8.x4.shared.b16 {%0,%1,%2,%3}, [%4];"
                 : "=r"(r[0]), "=r"(r[1]), "=r"(r[2]), "=r"(r[3]) : "r"(addr));
}
__device__ __forceinline__ void mma_bf16(float* d, const uint32_t* a,
                                         uint32_t b0, uint32_t b1) {
    asm volatile(
        "mma.sync.aligned.m16n8k16.row.col.f32.bf16.bf16.f32 "
        "{%0,%1,%2,%3}, {%4,%5,%6,%7}, {%8,%9}, {%0,%1,%2,%3};"
        : "+f"(d[0]), "+f"(d[1]), "+f"(d[2]), "+f"(d[3])
        : "r"(a[0]), "r"(a[1]), "r"(a[2]), "r"(a[3]), "r"(b0), "r"(b1));
}
__device__ __forceinline__ void split1(float v, __nv_bfloat16& h,
                                       __nv_bfloat16& l) {
    h = __float2bfloat16(v);
    l = __float2bfloat16(v - __bfloat162float(h));
}
// B-plane swizzle (64B rows, 4 chunks)
__device__ __forceinline__ uint32_t swz(uint32_t r, uint32_t c) {
    return r * 64u + ((c ^ ((r >> 1) & 3u)) << 4);
}
// A fp32 tile swizzle (128B rows, 8 chunks)
__device__ __forceinline__ uint32_t swzA(uint32_t r, uint32_t c) {
    return r * 128u + ((c ^ (r & 7u)) << 4);
}
__device__ __forceinline__ float2 lds64(uint32_t addr) {
    float2 v;
    asm volatile("ld.shared.v2.f32 {%0,%1}, [%2];"
                 : "=f"(v.x), "=f"(v.y) : "r"(addr));
    return v;
}
// fp32 pair -> (hi bf16x2, lo bf16x2); arithmetic identical to split1 pairs
__device__ __forceinline__ void cvt_pair(float2 p, uint32_t& hi, uint32_t& lo) {
    asm("cvt.rn.bf16x2.f32 %0, %1, %2;" : "=r"(hi) : "f"(p.y), "f"(p.x));
    const float hx = __uint_as_float(hi << 16);
    const float hy = __uint_as_float(hi & 0xffff0000u);
    const float lx = p.x - hx;
    const float ly = p.y - hy;
    asm("cvt.rn.bf16x2.f32 %0, %1, %2;" : "=r"(lo) : "f"(ly), "f"(lx));
}

// ---------------------------------------------------------------------------
// Small GEMM split-K body: 32 rows x 64 cols per CTA over K=[kbeg,kbeg+128),
// 256 threads, microtile 2x4, writes raw partial.
// ---------------------------------------------------------------------------
template <bool TRANSB>
__device__ __forceinline__
void gemm_k(const float* __restrict__ A,
            const float* __restrict__ B,
            float* __restrict__ outp,
            int row0, int col0, int kbeg)
{
    __shared__ float As[16][36];
    __shared__ float Bs[16][68];
    const int tid = threadIdx.x;
    const int tx = tid & 15, ty = tid >> 4;

    float acc[2][4];
    #pragma unroll
    for (int i = 0; i < 2; i++)
        #pragma unroll
        for (int j = 0; j < 4; j++) acc[i][j] = 0.0f;

    for (int kt = 0; kt < 8; kt++) {
        const int k0 = kbeg + kt * 16;
        if (tid < 128) {
            const int r = tid >> 2, k4 = (tid & 3) * 4;
            const float4 v = *(const float4*)&A[(size_t)(row0 + r) * Hh + k0 + k4];
            As[k4 + 0][r] = v.x; As[k4 + 1][r] = v.y;
            As[k4 + 2][r] = v.z; As[k4 + 3][r] = v.w;
        }
        if (TRANSB) {
            const int c = tid >> 2, k4 = (tid & 3) * 4;
            const float4 v = *(const float4*)&B[(size_t)(col0 + c) * Hh + k0 + k4];
            Bs[k4 + 0][c] = v.x; Bs[k4 + 1][c] = v.y;
            Bs[k4 + 2][c] = v.z; Bs[k4 + 3][c] = v.w;
        } else {
            const int k = tid >> 4, c4 = (tid & 15) * 4;
            *(float4*)&Bs[k][c4] = *(const float4*)&B[(size_t)(k0 + k) * Hh + col0 + c4];
        }
        __syncthreads();

        #pragma unroll
        for (int k = 0; k < 16; k++) {
            float a0 = As[k][ty * 2], a1 = As[k][ty * 2 + 1];
            float bb[4];
            #pragma unroll
            for (int j = 0; j < 4; j++) bb[j] = Bs[k][tx * 4 + j];
            #pragma unroll
            for (int j = 0; j < 4; j++) {
                acc[0][j] = fmaf(a0, bb[j], acc[0][j]);
                acc[1][j] = fmaf(a1, bb[j], acc[1][j]);
            }
        }
        __syncthreads();
    }

    #pragma unroll
    for (int i = 0; i < 2; i++)
        #pragma unroll
        for (int j = 0; j < 4; j++)
            outp[(size_t)(row0 + ty * 2 + i) * Hh + col0 + tx * 4 + j] = acc[i][j];
}

// ---------------------------------------------------------------------------
// Fused prep: blockIdx.x partition
//   [0,1024):    dual GEMM split-K: z = bx>>9, kc = (bx>>7)&3, rem = bx&127
//   [1024,1152): split_ws (Ws -> Bhi/Blo planes)
// ---------------------------------------------------------------------------
__global__ __launch_bounds__(256)
void prep_fused(const float* __restrict__ Ws,
                const float* __restrict__ tr,
                const float* __restrict__ Wr,
                const float* __restrict__ Wx,
                __nv_bfloat16* __restrict__ Bhi,
                __nv_bfloat16* __restrict__ Blo,
                float* __restrict__ dual_part)
{
    const int bx = blockIdx.x;
    if (bx < 1024) {
        const int z = bx >> 9, kc = (bx >> 7) & 3, rem = bx & 127;
        const int col0 = (rem & 7) * 64, row0 = (rem >> 3) * 32;
        float* outp = dual_part + (size_t)(z * 4 + kc) * HB;
        if (z == 0)
            gemm_k<false>(tr, Wr, outp, row0, col0, kc * 128);
        else
            gemm_k<true>(tr, Wx, outp, row0, col0, kc * 128);
    } else {
        const int base = (bx - 1024) * 1024 + threadIdx.x * 4;
        #pragma unroll
        for (int i = 0; i < 4; i++) {
            const int j = base + i;
            const int n = j >> 8, p = j & 255;
            __nv_bfloat162 h2, l2;
            split1(Ws[(2 * p) * Hh + n],     h2.x, l2.x);
            split1(Ws[(2 * p + 1) * Hh + n], h2.y, l2.y);
            ((__nv_bfloat162*)Bhi)[(size_t)n * (Hh / 2) + p] = h2;
            ((__nv_bfloat162*)Blo)[(size_t)n * (Hh / 2) + p] = l2;
        }
    }
}

// ---------------------------------------------------------------------------
// score kernel: CTA 128x128, K512, 3-stage k32, single sync/tile.
// A staged as RAW FP32 (swizzled); hi/lo fragments built in registers.
// B staged as bf16 planes + ldmatrix (unchanged).
// Wresp read as sum of 4 split-K partials (deterministic order).
// ---------------------------------------------------------------------------
#define A_W     4096u                 // A fp32 tile words (16KB)
#define PLANE_W 2048u                 // B plane words (8KB)
#define STG_W   (A_W + 2u * PLANE_W)  // 32KB
#define NSTG    3
#define SM_W    (NSTG * STG_W + 512)
#define SM_BYTES (SM_W * 4)

__global__ __launch_bounds__(256, 2)
void score_mma(const float* __restrict__ Afp,       // spk_emb fp32 [131072,512]
               const __nv_bfloat16* __restrict__ Bhi,
               const __nv_bfloat16* __restrict__ Blo,
               const float* __restrict__ dual_part, // Wresp partials at z=0
               const float* __restrict__ wvec,
               float* __restrict__ scores_part)
{
    extern __shared__ uint32_t smw[];
    float* WRs = (float*)(smw + NSTG * STG_W);
    float* WVs = WRs + 128;
    float* sp2 = WVs + 128;

    const int tid  = threadIdx.x;
    const int lane = tid & 31, wid = tid >> 5;
    const int wm = wid & 3, wn = wid >> 2;
    const int g  = lane >> 2, tg = lane & 3;
    const int col0 = blockIdx.x * 128;
    const int row0 = blockIdx.y * 128;
    const int b    = row0 >> 8;

    if (tid < 128) {
        const size_t o = (size_t)b * Hh + col0 + tid;
        WRs[tid] = ((dual_part[o] + dual_part[HB + o])
                  + (dual_part[2 * (size_t)HB + o] + dual_part[3 * (size_t)HB + o]));
        WVs[tid] = wvec[col0 + tid];
    }

    const uint32_t sbase = smem_u32(smw);

    // B ldmatrix lane offsets
    const uint32_t b_row = (lane & 7) | (((lane >> 4) & 1) << 3);
    const uint32_t b_chk = (lane >> 3) & 1;
    // A fragment lane constants
    const uint32_t wsel = ((2u * tg) & 3u) * 4u;   // byte offset within chunk
    const uint32_t cbase = (uint32_t)(tg >> 1);    // chunk sub-index

    // stage loader: A fp32 1024 chunks + Bhi 512 + Blo 512 = 2048, 8/thread
    auto load_stage = [&](int kk, int slot) {
        const uint32_t db = sbase + (uint32_t)slot * (STG_W * 4);
        #pragma unroll
        for (int i = 0; i < 8; i++) {
            const int idx = tid + 256 * i;
            if (i < 4) {
                const uint32_t r = (uint32_t)(idx >> 3), c = (uint32_t)(idx & 7);
                cp16(db + swzA(r, c),
                     Afp + (size_t)(row0 + r) * Hh + kk * 32 + c * 4);
            } else {
                const int j = idx - 1024;
                const int plane = j >> 9;            // 0 = Bhi, 1 = Blo (uniform)
                const uint32_t r = (uint32_t)((j >> 2) & 127), c = (uint32_t)(j & 3);
                const __nv_bfloat16* src = (plane == 0 ? Bhi : Blo)
                                           + (size_t)(col0 + r) * Hh + kk * 32 + c * 8;
                cp16(db + (A_W + plane * PLANE_W) * 4u + swz(r, c), src);
            }
        }
        asm volatile("cp.async.commit_group;" ::: "memory");
    };

    load_stage(0, 0);
    load_stage(1, 1);

    float acc[2][8][4];
    #pragma unroll
    for (int mt = 0; mt < 2; mt++)
        #pragma unroll
        for (int nt = 0; nt < 8; nt++)
            #pragma unroll
            for (int c = 0; c < 4; c++) acc[mt][nt][c] = 0.0f;

    #pragma unroll 1
    for (int kk = 0; kk < 16; kk++) {
        if (kk < 15) asm volatile("cp.async.wait_group 1;" ::: "memory");
        else         asm volatile("cp.async.wait_group 0;" ::: "memory");
        __syncthreads();

        if (kk + 2 < 16) load_stage(kk + 2, (kk + 2) % 3);

        const uint32_t stg  = sbase + (uint32_t)(kk % 3) * (STG_W * 4);
        const uint32_t pA   = stg;
        const uint32_t pBhi = stg + A_W * 4;
        const uint32_t pBlo = stg + (A_W + PLANE_W) * 4;

        #pragma unroll
        for (int ks = 0; ks < 2; ks++) {
            // ---- A fragments: fp32 -> hi/lo in registers ----
            uint32_t ahi[2][4], alo[2][4];
            const uint32_t c0 = 4u * ks + cbase;   // chunk for k-lo half
            const uint32_t c1 = c0 + 2u;           // chunk for k-hi half
            #pragma unroll
            for (int mt = 0; mt < 2; mt++) {
                const uint32_t rb = (uint32_t)(wm * 32 + mt * 16);
                const uint32_t r0 = rb + g, r1 = rb + 8 + g;
                const uint32_t x0 = pA + r0 * 128u + ((c0 ^ g) << 4) + wsel;
                const uint32_t x1 = pA + r1 * 128u + ((c0 ^ g) << 4) + wsel;
                const uint32_t x2 = pA + r0 * 128u + ((c1 ^ g) << 4) + wsel;
                const uint32_t x3 = pA + r1 * 128u + ((c1 ^ g) << 4) + wsel;
                cvt_pair(lds64(x0), ahi[mt][0], alo[mt][0]);
                cvt_pair(lds64(x1), ahi[mt][1], alo[mt][1]);
                cvt_pair(lds64(x2), ahi[mt][2], alo[mt][2]);
                cvt_pair(lds64(x3), ahi[mt][3], alo[mt][3]);
            }
            // ---- B fragments: ldmatrix on planes (unchanged) ----
            #pragma unroll
            for (int ntp = 0; ntp < 4; ntp++) {
                const uint32_t r = wn * 64 + ntp * 16 + b_row;
                const uint32_t off = swz(r, ks * 2 + b_chk);
                uint32_t bh[4], bl[4];
                ldsm4(bh, pBhi + off);
                ldsm4(bl, pBlo + off);
                #pragma unroll
                for (int half = 0; half < 2; half++) {
                    const int nt = ntp * 2 + half;
                    const uint32_t b0h = bh[half * 2], b1h = bh[half * 2 + 1];
                    const uint32_t b0l = bl[half * 2], b1l = bl[half * 2 + 1];
                    #pragma unroll
                    for (int mt = 0; mt < 2; mt++) {
                        mma_bf16(acc[mt][nt], ahi[mt], b0l, b1l);
                        mma_bf16(acc[mt][nt], alo[mt], b0h, b1h);
                        mma_bf16(acc[mt][nt], ahi[mt], b0h, b1h);
                    }
                }
            }
        }
    }

    #pragma unroll
    for (int mt = 0; mt < 2; mt++) {
        float plo = 0.0f, phi = 0.0f;
        #pragma unroll
        for (int nt = 0; nt < 8; nt++) {
            const int c0 = wn * 64 + nt * 8 + 2 * tg;
            const int c1 = c0 + 1;
            plo += tanh_fast(acc[mt][nt][0] + WRs[c0]) * WVs[c0]
                 + tanh_fast(acc[mt][nt][1] + WRs[c1]) * WVs[c1];
            phi += tanh_fast(acc[mt][nt][2] + WRs[c0]) * WVs[c0]
                 + tanh_fast(acc[mt][nt][3] + WRs[c1]) * WVs[c1];
        }
        plo += __shfl_xor_sync(0xFFFFFFFFu, plo, 1);
        plo += __shfl_xor_sync(0xFFFFFFFFu, plo, 2);
        phi += __shfl_xor_sync(0xFFFFFFFFu, phi, 1);
        phi += __shfl_xor_sync(0xFFFFFFFFu, phi, 2);
        if (tg == 0) {
            sp2[wn * 128 + wm * 32 + mt * 16 + g]     = plo;
            sp2[wn * 128 + wm * 32 + mt * 16 + 8 + g] = phi;
        }
    }
    __syncthreads();
    if (tid < 128)
        scores_part[(size_t)blockIdx.x * (Bsz * Nn) + row0 + tid] =
            sp2[tid] + sp2[128 + tid];
}

// ---------------------------------------------------------------------------
// Per-batch softmax + resp_s, split over h halves (unchanged from R10)
// ---------------------------------------------------------------------------
__global__ __launch_bounds__(256)
void softmax_weight_kernel(const float* __restrict__ scores_part,
                           const float* __restrict__ mask,
                           const float* __restrict__ emb,
                           float* __restrict__ alpha_out,
                           float* __restrict__ resps)
{
    const int b = blockIdx.x;
    const int half = blockIdx.y;
    const int tid = threadIdx.x;
    __shared__ float sa[256];
    __shared__ float red[256];

    const size_t i = (size_t)b * Nn + tid;
    float s = scores_part[i];
    s += scores_part[(size_t)(Bsz * Nn) + i];
    s += scores_part[(size_t)(2 * Bsz * Nn) + i];
    s += scores_part[(size_t)(3 * Bsz * Nn) + i];
    const float t = s * mask[i];

    red[tid] = t; __syncthreads();
    #pragma unroll
    for (int st = 128; st > 0; st >>= 1) {
        if (tid < st) red[tid] = fmaxf(red[tid], red[tid + st]);
        __syncthreads();
    }
    const float m = red[0];
    __syncthreads();

    const float e = __expf(t - m);
    red[tid] = e; __syncthreads();
    #pragma unroll
    for (int st = 128; st > 0; st >>= 1) {
        if (tid < st) red[tid] += red[tid + st];
        __syncthreads();
    }
    const float a = e / red[0];

    if (half == 0) alpha_out[i] = a;
    sa[tid] = a;
    __syncthreads();

    const int h = half * 256 + tid;
    const float* eb = emb + (size_t)b * Nn * Hh + h;
    float c0 = 0.f, c1 = 0.f, c2 = 0.f, c3 = 0.f;
    float c4 = 0.f, c5 = 0.f, c6 = 0.f, c7 = 0.f;
    #pragma unroll 1
    for (int n = 0; n < Nn; n += 8) {
        c0 = fmaf(sa[n    ], eb[(size_t)(n    ) * Hh], c0);
        c1 = fmaf(sa[n + 1], eb[(size_t)(n + 1) * Hh], c1);
        c2 = fmaf(sa[n + 2], eb[(size_t)(n + 2) * Hh], c2);
        c3 = fmaf(sa[n + 3], eb[(size_t)(n + 3) * Hh], c3);
        c4 = fmaf(sa[n + 4], eb[(size_t)(n + 4) * Hh], c4);
        c5 = fmaf(sa[n + 5], eb[(size_t)(n + 5) * Hh], c5);
        c6 = fmaf(sa[n + 6], eb[(size_t)(n + 6) * Hh], c6);
        c7 = fmaf(sa[n + 7], eb[(size_t)(n + 7) * Hh], c7);
    }
    resps[b * Hh + h] = ((c0 + c1) + (c2 + c3)) + ((c4 + c5) + (c6 + c7));
}

// ---------------------------------------------------------------------------
// Final GEMM split-K: partial = presps @ Wp^T over K chunk
// ---------------------------------------------------------------------------
__global__ __launch_bounds__(256)
void gemm_final_k(const float* __restrict__ A,
                  const float* __restrict__ B,
                  float* __restrict__ fin_part)
{
    const int kc = blockIdx.z;
    gemm_k<true>(A, B, fin_part + (size_t)kc * HB,
                 blockIdx.y * 32, blockIdx.x * 64, kc * 128);
}

// combine: out = tanh(sum fin partials + sum rx partials)   (deterministic)
__global__ __launch_bounds__(512)
void combine_final(const float* __restrict__ fin_part,
                   const float* __restrict__ dual_part,   // rx at z=1
                   float* __restrict__ out)
{
    const size_t idx = (size_t)blockIdx.x * 512 + threadIdx.x;
    float f = ((fin_part[idx] + fin_part[HB + idx])
             + (fin_part[2 * (size_t)HB + idx] + fin_part[3 * (size_t)HB + idx]));
    const float* rx = dual_part + 4 * (size_t)HB;
    float r = ((rx[idx] + rx[HB + idx])
             + (rx[2 * (size_t)HB + idx] + rx[3 * (size_t)HB + idx]));
    out[idx] = tanhf(f + r);
}

// ---------------------------------------------------------------------------
extern "C" void kernel_launch(void* const* d_in, const int* in_sizes, int n_in,
                              void* d_out, int out_size)
{
    const float* spk  = (const float*)d_in[0];
    const float* mask = (const float*)d_in[1];
    const float* tr   = (const float*)d_in[2];
    const float* Ws   = (const float*)d_in[3];
    const float* Wr   = (const float*)d_in[4];
    const float* w    = (const float*)d_in[5];
    const float* Wp   = (const float*)d_in[6];
    const float* Wx   = (const float*)d_in[7];

    float* out = (float*)d_out;
    float* resp_out  = out;
    float* alpha_out = out + Bsz * Hh;

    float *pspart, *presps, *pdual, *pfin;
    __nv_bfloat16 *pBhi, *pBlo;
    cudaGetSymbolAddress((void**)&pspart, g_scores_part);
    cudaGetSymbolAddress((void**)&presps, g_resps);
    cudaGetSymbolAddress((void**)&pdual, g_dual_part);
    cudaGetSymbolAddress((void**)&pfin, g_fin_part);
    cudaGetSymbolAddress((void**)&pBhi, g_Bhi);
    cudaGetSymbolAddress((void**)&pBlo, g_Blo);

    static bool attr_set = false;
    if (!attr_set) {
        cudaFuncSetAttribute(score_mma,
                             cudaFuncAttributeMaxDynamicSharedMemorySize,
                             SM_BYTES);
        attr_set = true;
    }

    prep_fused<<<1152, 256>>>(Ws, tr, Wr, Wx, pBhi, pBlo, pdual);
    score_mma<<<dim3(4, 1024), 256, SM_BYTES>>>(spk, pBhi, pBlo,
                                                pdual, w, pspart);
    softmax_weight_kernel<<<dim3(512, 2), 256>>>(pspart, mask, spk,
                                                 alpha_out, presps);
    gemm_final_k<<<dim3(8, 16, 4), 256>>>(presps, Wp, pfin);
    combine_final<<<512, 512>>>(pfin, pdual, resp_out);
}

// round 12
// speedup vs baseline: 2.0490x; 1.0023x over previous
#include <cuda_runtime.h>
#include <cuda_bf16.h>
#include <cstdint>

// ---------------------------------------------------------------------------
// Spk_Attention: B=512, N=256, H=512. sm_103 plain target -> mma.sync bf16
// m16n8k16 3xBF16.  R12: split-K=8 on dual-prep and final GEMMs (serial
// chain 4 tiles); score_mma byte-identical to R11.
// ---------------------------------------------------------------------------

#define Bsz 512
#define Nn  256
#define Hh  512
#define HB  (Hh * Hh)          // 262144

__device__ float g_scores_part[4 * Bsz * Nn];
__device__ float g_resps[Bsz * Hh];
__device__ float g_dual_part[16 * HB];  // [z(2)][kc(8)][512*512]
__device__ float g_fin_part[8 * HB];    // [kc(8)][512*512]
__device__ __nv_bfloat16 g_Bhi[HB];     // WsT hi plane [n][k]
__device__ __nv_bfloat16 g_Blo[HB];

// ---------------- helpers --------------------------------------------------
__device__ __forceinline__ float tanh_fast(float x) {
    float y;
    asm("tanh.approx.f32 %0, %1;" : "=f"(y) : "f"(x));
    return y;
}
__device__ __forceinline__ uint32_t smem_u32(const void* p) {
    uint32_t a;
    asm("{ .reg .u64 t; cvta.to.shared.u64 t, %1; cvt.u32.u64 %0, t; }"
        : "=r"(a) : "l"(p));
    return a;
}
__device__ __forceinline__ void cp16(uint32_t dst, const void* src) {
    asm volatile("cp.async.cg.shared.global [%0], [%1], 16;"
                 :: "r"(dst), "l"(src) : "memory");
}
__device__ __forceinline__ void ldsm4(uint32_t* r, uint32_t addr) {
    asm volatile("ldmatrix.sync.aligned.m8n8.x4.shared.b16 {%0,%1,%2,%3}, [%4];"
                 : "=r"(r[0]), "=r"(r[1]), "=r"(r[2]), "=r"(r[3]) : "r"(addr));
}
__device__ __forceinline__ void mma_bf16(float* d, const uint32_t* a,
                                         uint32_t b0, uint32_t b1) {
    asm volatile(
        "mma.sync.aligned.m16n8k16.row.col.f32.bf16.bf16.f32 "
        "{%0,%1,%2,%3}, {%4,%5,%6,%7}, {%8,%9}, {%0,%1,%2,%3};"
        : "+f"(d[0]), "+f"(d[1]), "+f"(d[2]), "+f"(d[3])
        : "r"(a[0]), "r"(a[1]), "r"(a[2]), "r"(a[3]), "r"(b0), "r"(b1));
}
__device__ __forceinline__ void split1(float v, __nv_bfloat16& h,
                                       __nv_bfloat16& l) {
    h = __float2bfloat16(v);
    l = __float2bfloat16(v - __bfloat162float(h));
}
// B-plane swizzle (64B rows, 4 chunks)
__device__ __forceinline__ uint32_t swz(uint32_t r, uint32_t c) {
    return r * 64u + ((c ^ ((r >> 1) & 3u)) << 4);
}
// A fp32 tile swizzle (128B rows, 8 chunks)
__device__ __forceinline__ uint32_t swzA(uint32_t r, uint32_t c) {
    return r * 128u + ((c ^ (r & 7u)) << 4);
}
__device__ __forceinline__ float2 lds64(uint32_t addr) {
    float2 v;
    asm volatile("ld.shared.v2.f32 {%0,%1}, [%2];"
                 : "=f"(v.x), "=f"(v.y) : "r"(addr));
    return v;
}
// fp32 pair -> (hi bf16x2, lo bf16x2)
__device__ __forceinline__ void cvt_pair(float2 p, uint32_t& hi, uint32_t& lo) {
    asm("cvt.rn.bf16x2.f32 %0, %1, %2;" : "=r"(hi) : "f"(p.y), "f"(p.x));
    const float hx = __uint_as_float(hi << 16);
    const float hy = __uint_as_float(hi & 0xffff0000u);
    const float lx = p.x - hx;
    const float ly = p.y - hy;
    asm("cvt.rn.bf16x2.f32 %0, %1, %2;" : "=r"(lo) : "f"(ly), "f"(lx));
}

// ---------------------------------------------------------------------------
// Small GEMM split-K body: 32 rows x 64 cols per CTA over K=[kbeg,kbeg+64),
// (4 serial k16 tiles), 256 threads, microtile 2x4, writes raw partial.
// ---------------------------------------------------------------------------
template <bool TRANSB>
__device__ __forceinline__
void gemm_k(const float* __restrict__ A,
            const float* __restrict__ B,
            float* __restrict__ outp,
            int row0, int col0, int kbeg)
{
    __shared__ float As[16][36];
    __shared__ float Bs[16][68];
    const int tid = threadIdx.x;
    const int tx = tid & 15, ty = tid >> 4;

    float acc[2][4];
    #pragma unroll
    for (int i = 0; i < 2; i++)
        #pragma unroll
        for (int j = 0; j < 4; j++) acc[i][j] = 0.0f;

    #pragma unroll
    for (int kt = 0; kt < 4; kt++) {
        const int k0 = kbeg + kt * 16;
        if (tid < 128) {
            const int r = tid >> 2, k4 = (tid & 3) * 4;
            const float4 v = *(const float4*)&A[(size_t)(row0 + r) * Hh + k0 + k4];
            As[k4 + 0][r] = v.x; As[k4 + 1][r] = v.y;
            As[k4 + 2][r] = v.z; As[k4 + 3][r] = v.w;
        }
        if (TRANSB) {
            const int c = tid >> 2, k4 = (tid & 3) * 4;
            const float4 v = *(const float4*)&B[(size_t)(col0 + c) * Hh + k0 + k4];
            Bs[k4 + 0][c] = v.x; Bs[k4 + 1][c] = v.y;
            Bs[k4 + 2][c] = v.z; Bs[k4 + 3][c] = v.w;
        } else {
            const int k = tid >> 4, c4 = (tid & 15) * 4;
            *(float4*)&Bs[k][c4] = *(const float4*)&B[(size_t)(k0 + k) * Hh + col0 + c4];
        }
        __syncthreads();

        #pragma unroll
        for (int k = 0; k < 16; k++) {
            float a0 = As[k][ty * 2], a1 = As[k][ty * 2 + 1];
            float bb[4];
            #pragma unroll
            for (int j = 0; j < 4; j++) bb[j] = Bs[k][tx * 4 + j];
            #pragma unroll
            for (int j = 0; j < 4; j++) {
                acc[0][j] = fmaf(a0, bb[j], acc[0][j]);
                acc[1][j] = fmaf(a1, bb[j], acc[1][j]);
            }
        }
        __syncthreads();
    }

    #pragma unroll
    for (int i = 0; i < 2; i++)
        #pragma unroll
        for (int j = 0; j < 4; j++)
            outp[(size_t)(row0 + ty * 2 + i) * Hh + col0 + tx * 4 + j] = acc[i][j];
}

// ---------------------------------------------------------------------------
// Fused prep: blockIdx.x partition
//   [0,2048):    dual GEMM split-K8: z = bx>>10, kc = (bx>>7)&7, rem = bx&127
//   [2048,2176): split_ws (Ws -> Bhi/Blo planes)
// ---------------------------------------------------------------------------
__global__ __launch_bounds__(256)
void prep_fused(const float* __restrict__ Ws,
                const float* __restrict__ tr,
                const float* __restrict__ Wr,
                const float* __restrict__ Wx,
                __nv_bfloat16* __restrict__ Bhi,
                __nv_bfloat16* __restrict__ Blo,
                float* __restrict__ dual_part)
{
    const int bx = blockIdx.x;
    if (bx < 2048) {
        const int z = bx >> 10, kc = (bx >> 7) & 7, rem = bx & 127;
        const int col0 = (rem & 7) * 64, row0 = (rem >> 3) * 32;
        float* outp = dual_part + (size_t)(z * 8 + kc) * HB;
        if (z == 0)
            gemm_k<false>(tr, Wr, outp, row0, col0, kc * 64);
        else
            gemm_k<true>(tr, Wx, outp, row0, col0, kc * 64);
    } else {
        const int base = (bx - 2048) * 1024 + threadIdx.x * 4;
        #pragma unroll
        for (int i = 0; i < 4; i++) {
            const int j = base + i;
            const int n = j >> 8, p = j & 255;
            __nv_bfloat162 h2, l2;
            split1(Ws[(2 * p) * Hh + n],     h2.x, l2.x);
            split1(Ws[(2 * p + 1) * Hh + n], h2.y, l2.y);
            ((__nv_bfloat162*)Bhi)[(size_t)n * (Hh / 2) + p] = h2;
            ((__nv_bfloat162*)Blo)[(size_t)n * (Hh / 2) + p] = l2;
        }
    }
}

// ---------------------------------------------------------------------------
// score kernel (logic identical to R11; WR now sums 8 split-K partials)
// ---------------------------------------------------------------------------
#define A_W     4096u
#define PLANE_W 2048u
#define STG_W   (A_W + 2u * PLANE_W)
#define NSTG    3
#define SM_W    (NSTG * STG_W + 512)
#define SM_BYTES (SM_W * 4)

__global__ __launch_bounds__(256, 2)
void score_mma(const float* __restrict__ Afp,
               const __nv_bfloat16* __restrict__ Bhi,
               const __nv_bfloat16* __restrict__ Blo,
               const float* __restrict__ dual_part,
               const float* __restrict__ wvec,
               float* __restrict__ scores_part)
{
    extern __shared__ uint32_t smw[];
    float* WRs = (float*)(smw + NSTG * STG_W);
    float* WVs = WRs + 128;
    float* sp2 = WVs + 128;

    const int tid  = threadIdx.x;
    const int lane = tid & 31, wid = tid >> 5;
    const int wm = wid & 3, wn = wid >> 2;
    const int g  = lane >> 2, tg = lane & 3;
    const int col0 = blockIdx.x * 128;
    const int row0 = blockIdx.y * 128;
    const int b    = row0 >> 8;

    if (tid < 128) {
        const size_t o = (size_t)b * Hh + col0 + tid;
        float s = ((dual_part[o] + dual_part[HB + o])
                 + (dual_part[2 * (size_t)HB + o] + dual_part[3 * (size_t)HB + o]));
        s += ((dual_part[4 * (size_t)HB + o] + dual_part[5 * (size_t)HB + o])
            + (dual_part[6 * (size_t)HB + o] + dual_part[7 * (size_t)HB + o]));
        WRs[tid] = s;
        WVs[tid] = wvec[col0 + tid];
    }

    const uint32_t sbase = smem_u32(smw);

    const uint32_t b_row = (lane & 7) | (((lane >> 4) & 1) << 3);
    const uint32_t b_chk = (lane >> 3) & 1;
    const uint32_t wsel = ((2u * tg) & 3u) * 4u;
    const uint32_t cbase = (uint32_t)(tg >> 1);

    auto load_stage = [&](int kk, int slot) {
        const uint32_t db = sbase + (uint32_t)slot * (STG_W * 4);
        #pragma unroll
        for (int i = 0; i < 8; i++) {
            const int idx = tid + 256 * i;
            if (i < 4) {
                const uint32_t r = (uint32_t)(idx >> 3), c = (uint32_t)(idx & 7);
                cp16(db + swzA(r, c),
                     Afp + (size_t)(row0 + r) * Hh + kk * 32 + c * 4);
            } else {
                const int j = idx - 1024;
                const int plane = j >> 9;
                const uint32_t r = (uint32_t)((j >> 2) & 127), c = (uint32_t)(j & 3);
                const __nv_bfloat16* src = (plane == 0 ? Bhi : Blo)
                                           + (size_t)(col0 + r) * Hh + kk * 32 + c * 8;
                cp16(db + (A_W + plane * PLANE_W) * 4u + swz(r, c), src);
            }
        }
        asm volatile("cp.async.commit_group;" ::: "memory");
    };

    load_stage(0, 0);
    load_stage(1, 1);

    float acc[2][8][4];
    #pragma unroll
    for (int mt = 0; mt < 2; mt++)
        #pragma unroll
        for (int nt = 0; nt < 8; nt++)
            #pragma unroll
            for (int c = 0; c < 4; c++) acc[mt][nt][c] = 0.0f;

    #pragma unroll 1
    for (int kk = 0; kk < 16; kk++) {
        if (kk < 15) asm volatile("cp.async.wait_group 1;" ::: "memory");
        else         asm volatile("cp.async.wait_group 0;" ::: "memory");
        __syncthreads();

        if (kk + 2 < 16) load_stage(kk + 2, (kk + 2) % 3);

        const uint32_t stg  = sbase + (uint32_t)(kk % 3) * (STG_W * 4);
        const uint32_t pA   = stg;
        const uint32_t pBhi = stg + A_W * 4;
        const uint32_t pBlo = stg + (A_W + PLANE_W) * 4;

        #pragma unroll
        for (int ks = 0; ks < 2; ks++) {
            uint32_t ahi[2][4], alo[2][4];
            const uint32_t c0 = 4u * ks + cbase;
            const uint32_t c1 = c0 + 2u;
            #pragma unroll
            for (int mt = 0; mt < 2; mt++) {
                const uint32_t rb = (uint32_t)(wm * 32 + mt * 16);
                const uint32_t r0 = rb + g, r1 = rb + 8 + g;
                const uint32_t x0 = pA + r0 * 128u + ((c0 ^ g) << 4) + wsel;
                const uint32_t x1 = pA + r1 * 128u + ((c0 ^ g) << 4) + wsel;
                const uint32_t x2 = pA + r0 * 128u + ((c1 ^ g) << 4) + wsel;
                const uint32_t x3 = pA + r1 * 128u + ((c1 ^ g) << 4) + wsel;
                cvt_pair(lds64(x0), ahi[mt][0], alo[mt][0]);
                cvt_pair(lds64(x1), ahi[mt][1], alo[mt][1]);
                cvt_pair(lds64(x2), ahi[mt][2], alo[mt][2]);
                cvt_pair(lds64(x3), ahi[mt][3], alo[mt][3]);
            }
            #pragma unroll
            for (int ntp = 0; ntp < 4; ntp++) {
                const uint32_t r = wn * 64 + ntp * 16 + b_row;
                const uint32_t off = swz(r, ks * 2 + b_chk);
                uint32_t bh[4], bl[4];
                ldsm4(bh, pBhi + off);
                ldsm4(bl, pBlo + off);
                #pragma unroll
                for (int half = 0; half < 2; half++) {
                    const int nt = ntp * 2 + half;
                    const uint32_t b0h = bh[half * 2], b1h = bh[half * 2 + 1];
                    const uint32_t b0l = bl[half * 2], b1l = bl[half * 2 + 1];
                    #pragma unroll
                    for (int mt = 0; mt < 2; mt++) {
                        mma_bf16(acc[mt][nt], ahi[mt], b0l, b1l);
                        mma_bf16(acc[mt][nt], alo[mt], b0h, b1h);
                        mma_bf16(acc[mt][nt], ahi[mt], b0h, b1h);
                    }
                }
            }
        }
    }

    #pragma unroll
    for (int mt = 0; mt < 2; mt++) {
        float plo = 0.0f, phi = 0.0f;
        #pragma unroll
        for (int nt = 0; nt < 8; nt++) {
            const int c0 = wn * 64 + nt * 8 + 2 * tg;
            const int c1 = c0 + 1;
            plo += tanh_fast(acc[mt][nt][0] + WRs[c0]) * WVs[c0]
                 + tanh_fast(acc[mt][nt][1] + WRs[c1]) * WVs[c1];
            phi += tanh_fast(acc[mt][nt][2] + WRs[c0]) * WVs[c0]
                 + tanh_fast(acc[mt][nt][3] + WRs[c1]) * WVs[c1];
        }
        plo += __shfl_xor_sync(0xFFFFFFFFu, plo, 1);
        plo += __shfl_xor_sync(0xFFFFFFFFu, plo, 2);
        phi += __shfl_xor_sync(0xFFFFFFFFu, phi, 1);
        phi += __shfl_xor_sync(0xFFFFFFFFu, phi, 2);
        if (tg == 0) {
            sp2[wn * 128 + wm * 32 + mt * 16 + g]     = plo;
            sp2[wn * 128 + wm * 32 + mt * 16 + 8 + g] = phi;
        }
    }
    __syncthreads();
    if (tid < 128)
        scores_part[(size_t)blockIdx.x * (Bsz * Nn) + row0 + tid] =
            sp2[tid] + sp2[128 + tid];
}

// ---------------------------------------------------------------------------
// Per-batch softmax + resp_s (unchanged from R10/R11)
// ---------------------------------------------------------------------------
__global__ __launch_bounds__(256)
void softmax_weight_kernel(const float* __restrict__ scores_part,
                           const float* __restrict__ mask,
                           const float* __restrict__ emb,
                           float* __restrict__ alpha_out,
                           float* __restrict__ resps)
{
    const int b = blockIdx.x;
    const int half = blockIdx.y;
    const int tid = threadIdx.x;
    __shared__ float sa[256];
    __shared__ float red[256];

    const size_t i = (size_t)b * Nn + tid;
    float s = scores_part[i];
    s += scores_part[(size_t)(Bsz * Nn) + i];
    s += scores_part[(size_t)(2 * Bsz * Nn) + i];
    s += scores_part[(size_t)(3 * Bsz * Nn) + i];
    const float t = s * mask[i];

    red[tid] = t; __syncthreads();
    #pragma unroll
    for (int st = 128; st > 0; st >>= 1) {
        if (tid < st) red[tid] = fmaxf(red[tid], red[tid + st]);
        __syncthreads();
    }
    const float m = red[0];
    __syncthreads();

    const float e = __expf(t - m);
    red[tid] = e; __syncthreads();
    #pragma unroll
    for (int st = 128; st > 0; st >>= 1) {
        if (tid < st) red[tid] += red[tid + st];
        __syncthreads();
    }
    const float a = e / red[0];

    if (half == 0) alpha_out[i] = a;
    sa[tid] = a;
    __syncthreads();

    const int h = half * 256 + tid;
    const float* eb = emb + (size_t)b * Nn * Hh + h;
    float c0 = 0.f, c1 = 0.f, c2 = 0.f, c3 = 0.f;
    float c4 = 0.f, c5 = 0.f, c6 = 0.f, c7 = 0.f;
    #pragma unroll 1
    for (int n = 0; n < Nn; n += 8) {
        c0 = fmaf(sa[n    ], eb[(size_t)(n    ) * Hh], c0);
        c1 = fmaf(sa[n + 1], eb[(size_t)(n + 1) * Hh], c1);
        c2 = fmaf(sa[n + 2], eb[(size_t)(n + 2) * Hh], c2);
        c3 = fmaf(sa[n + 3], eb[(size_t)(n + 3) * Hh], c3);
        c4 = fmaf(sa[n + 4], eb[(size_t)(n + 4) * Hh], c4);
        c5 = fmaf(sa[n + 5], eb[(size_t)(n + 5) * Hh], c5);
        c6 = fmaf(sa[n + 6], eb[(size_t)(n + 6) * Hh], c6);
        c7 = fmaf(sa[n + 7], eb[(size_t)(n + 7) * Hh], c7);
    }
    resps[b * Hh + h] = ((c0 + c1) + (c2 + c3)) + ((c4 + c5) + (c6 + c7));
}

// ---------------------------------------------------------------------------
// Final GEMM split-K8: partial = presps @ Wp^T over 64-wide K chunk
// ---------------------------------------------------------------------------
__global__ __launch_bounds__(256)
void gemm_final_k(const float* __restrict__ A,
                  const float* __restrict__ B,
                  float* __restrict__ fin_part)
{
    const int kc = blockIdx.z;
    gemm_k<true>(A, B, fin_part + (size_t)kc * HB,
                 blockIdx.y * 32, blockIdx.x * 64, kc * 64);
}

// combine: out = tanh(sum fin partials + sum rx partials)   (deterministic)
__global__ __launch_bounds__(512)
void combine_final(const float* __restrict__ fin_part,
                   const float* __restrict__ dual_part,
                   float* __restrict__ out)
{
    const size_t idx = (size_t)blockIdx.x * 512 + threadIdx.x;
    float f = ((fin_part[idx] + fin_part[HB + idx])
             + (fin_part[2 * (size_t)HB + idx] + fin_part[3 * (size_t)HB + idx]));
    f += ((fin_part[4 * (size_t)HB + idx] + fin_part[5 * (size_t)HB + idx])
        + (fin_part[6 * (size_t)HB + idx] + fin_part[7 * (size_t)HB + idx]));
    const float* rx = dual_part + 8 * (size_t)HB;
    float r = ((rx[idx] + rx[HB + idx])
             + (rx[2 * (size_t)HB + idx] + rx[3 * (size_t)HB + idx]));
    r += ((rx[4 * (size_t)HB + idx] + rx[5 * (size_t)HB + idx])
        + (rx[6 * (size_t)HB + idx] + rx[7 * (size_t)HB + idx]));
    out[idx] = tanhf(f + r);
}

// ---------------------------------------------------------------------------
extern "C" void kernel_launch(void* const* d_in, const int* in_sizes, int n_in,
                              void* d_out, int out_size)
{
    const float* spk  = (const float*)d_in[0];
    const float* mask = (const float*)d_in[1];
    const float* tr   = (const float*)d_in[2];
    const float* Ws   = (const float*)d_in[3];
    const float* Wr   = (const float*)d_in[4];
    const float* w    = (const float*)d_in[5];
    const float* Wp   = (const float*)d_in[6];
    const float* Wx   = (const float*)d_in[7];

    float* out = (float*)d_out;
    float* resp_out  = out;
    float* alpha_out = out + Bsz * Hh;

    float *pspart, *presps, *pdual, *pfin;
    __nv_bfloat16 *pBhi, *pBlo;
    cudaGetSymbolAddress((void**)&pspart, g_scores_part);
    cudaGetSymbolAddress((void**)&presps, g_resps);
    cudaGetSymbolAddress((void**)&pdual, g_dual_part);
    cudaGetSymbolAddress((void**)&pfin, g_fin_part);
    cudaGetSymbolAddress((void**)&pBhi, g_Bhi);
    cudaGetSymbolAddress((void**)&pBlo, g_Blo);

    static bool attr_set = false;
    if (!attr_set) {
        cudaFuncSetAttribute(score_mma,
                             cudaFuncAttributeMaxDynamicSharedMemorySize,
                             SM_BYTES);
        attr_set = true;
    }

    prep_fused<<<2176, 256>>>(Ws, tr, Wr, Wx, pBhi, pBlo, pdual);
    score_mma<<<dim3(4, 1024), 256, SM_BYTES>>>(spk, pBhi, pBlo,
                                                pdual, w, pspart);
    softmax_weight_kernel<<<dim3(512, 2), 256>>>(pspart, mask, spk,
                                                 alpha_out, presps);
    gemm_final_k<<<dim3(8, 16, 8), 256>>>(presps, Wp, pfin);
    combine_final<<<512, 512>>>(pfin, pdual, resp_out);
}

// round 13
// speedup vs baseline: 2.0881x; 1.0191x over previous
#include <cuda_runtime.h>
#include <cuda_bf16.h>
#include <cstdint>

// ---------------------------------------------------------------------------
// Spk_Attention: B=512, N=256, H=512. sm_103 plain target -> mma.sync bf16
// m16n8k16 3xBF16.  R13: small GEMMs rebuilt LDS-lean (4x4 microtile,
// 64x64 tiles, split-K4); score_mma byte-identical to R11/R12.
// ---------------------------------------------------------------------------

#define Bsz 512
#define Nn  256
#define Hh  512
#define HB  (Hh * Hh)          // 262144

__device__ float g_scores_part[4 * Bsz * Nn];
__device__ float g_resps[Bsz * Hh];
__device__ float g_dual_part[8 * HB];   // [z(2)][kc(4)][512*512]
__device__ float g_fin_part[4 * HB];    // [kc(4)][512*512]
__device__ __nv_bfloat16 g_Bhi[HB];     // WsT hi plane [n][k]
__device__ __nv_bfloat16 g_Blo[HB];

// ---------------- helpers --------------------------------------------------
__device__ __forceinline__ float tanh_fast(float x) {
    float y;
    asm("tanh.approx.f32 %0, %1;" : "=f"(y) : "f"(x));
    return y;
}
__device__ __forceinline__ uint32_t smem_u32(const void* p) {
    uint32_t a;
    asm("{ .reg .u64 t; cvta.to.shared.u64 t, %1; cvt.u32.u64 %0, t; }"
        : "=r"(a) : "l"(p));
    return a;
}
__device__ __forceinline__ void cp16(uint32_t dst, const void* src) {
    asm volatile("cp.async.cg.shared.global [%0], [%1], 16;"
                 :: "r"(dst), "l"(src) : "memory");
}
__device__ __forceinline__ void ldsm4(uint32_t* r, uint32_t addr) {
    asm volatile("ldmatrix.sync.aligned.m8n8.x4.shared.b16 {%0,%1,%2,%3}, [%4];"
                 : "=r"(r[0]), "=r"(r[1]), "=r"(r[2]), "=r"(r[3]) : "r"(addr));
}
__device__ __forceinline__ void mma_bf16(float* d, const uint32_t* a,
                                         uint32_t b0, uint32_t b1) {
    asm volatile(
        "mma.sync.aligned.m16n8k16.row.col.f32.bf16.bf16.f32 "
        "{%0,%1,%2,%3}, {%4,%5,%6,%7}, {%8,%9}, {%0,%1,%2,%3};"
        : "+f"(d[0]), "+f"(d[1]), "+f"(d[2]), "+f"(d[3])
        : "r"(a[0]), "r"(a[1]), "r"(a[2]), "r"(a[3]), "r"(b0), "r"(b1));
}
__device__ __forceinline__ void split1(float v, __nv_bfloat16& h,
                                       __nv_bfloat16& l) {
    h = __float2bfloat16(v);
    l = __float2bfloat16(v - __bfloat162float(h));
}
// B-plane swizzle (64B rows, 4 chunks)
__device__ __forceinline__ uint32_t swz(uint32_t r, uint32_t c) {
    return r * 64u + ((c ^ ((r >> 1) & 3u)) << 4);
}
// A fp32 tile swizzle (128B rows, 8 chunks)
__device__ __forceinline__ uint32_t swzA(uint32_t r, uint32_t c) {
    return r * 128u + ((c ^ (r & 7u)) << 4);
}
__device__ __forceinline__ float2 lds64(uint32_t addr) {
    float2 v;
    asm volatile("ld.shared.v2.f32 {%0,%1}, [%2];"
                 : "=f"(v.x), "=f"(v.y) : "r"(addr));
    return v;
}
// fp32 pair -> (hi bf16x2, lo bf16x2)
__device__ __forceinline__ void cvt_pair(float2 p, uint32_t& hi, uint32_t& lo) {
    asm("cvt.rn.bf16x2.f32 %0, %1, %2;" : "=r"(hi) : "f"(p.y), "f"(p.x));
    const float hx = __uint_as_float(hi << 16);
    const float hy = __uint_as_float(hi & 0xffff0000u);
    const float lx = p.x - hx;
    const float ly = p.y - hy;
    asm("cvt.rn.bf16x2.f32 %0, %1, %2;" : "=r"(lo) : "f"(ly), "f"(lx));
}

// ---------------------------------------------------------------------------
// Small GEMM split-K body: 64 rows x 64 cols per CTA over K=[kbeg,kbeg+128)
// (8 serial k16 tiles), 256 threads (16x16), microtile 4x4, LDS.128 loads.
// ---------------------------------------------------------------------------
template <bool TRANSB>
__device__ __forceinline__
void gemm_k(const float* __restrict__ A,
            const float* __restrict__ B,
            float* __restrict__ outp,
            int row0, int col0, int kbeg)
{
    __shared__ float As[16][68];   // [k][row], 272B rows (16B aligned)
    __shared__ float Bs[16][68];   // [k][col]
    const int tid = threadIdx.x;
    const int tx = tid & 15, ty = tid >> 4;

    float acc[4][4];
    #pragma unroll
    for (int i = 0; i < 4; i++)
        #pragma unroll
        for (int j = 0; j < 4; j++) acc[i][j] = 0.0f;

    #pragma unroll 1
    for (int kt = 0; kt < 8; kt++) {
        const int k0 = kbeg + kt * 16;
        {   // A: 64 rows x 16 k, one float4 per thread, transposed store
            const int r = tid >> 2, k4 = (tid & 3) * 4;
            const float4 v = *(const float4*)&A[(size_t)(row0 + r) * Hh + k0 + k4];
            As[k4 + 0][r] = v.x; As[k4 + 1][r] = v.y;
            As[k4 + 2][r] = v.z; As[k4 + 3][r] = v.w;
        }
        if (TRANSB) {
            const int c = tid >> 2, k4 = (tid & 3) * 4;
            const float4 v = *(const float4*)&B[(size_t)(col0 + c) * Hh + k0 + k4];
            Bs[k4 + 0][c] = v.x; Bs[k4 + 1][c] = v.y;
            Bs[k4 + 2][c] = v.z; Bs[k4 + 3][c] = v.w;
        } else {
            const int k = tid >> 4, c4 = (tid & 15) * 4;
            *(float4*)&Bs[k][c4] = *(const float4*)&B[(size_t)(k0 + k) * Hh + col0 + c4];
        }
        __syncthreads();

        #pragma unroll
        for (int k = 0; k < 16; k++) {
            const float4 a = *(const float4*)&As[k][ty * 4];
            const float4 bb = *(const float4*)&Bs[k][tx * 4];
            const float av[4] = {a.x, a.y, a.z, a.w};
            const float bv[4] = {bb.x, bb.y, bb.z, bb.w};
            #pragma unroll
            for (int i = 0; i < 4; i++)
                #pragma unroll
                for (int j = 0; j < 4; j++)
                    acc[i][j] = fmaf(av[i], bv[j], acc[i][j]);
        }
        __syncthreads();
    }

    #pragma unroll
    for (int i = 0; i < 4; i++)
        #pragma unroll
        for (int j = 0; j < 4; j++)
            outp[(size_t)(row0 + ty * 4 + i) * Hh + col0 + tx * 4 + j] = acc[i][j];
}

// ---------------------------------------------------------------------------
// Fused prep: blockIdx.x partition
//   [0,512):   dual GEMM split-K4: z = bx>>8, kc = (bx>>6)&3, rem = bx&63
//              (64x64 tiles: col0 = (rem&7)*64, row0 = (rem>>3)*64)
//   [512,640): split_ws (Ws -> Bhi/Blo planes)
// ---------------------------------------------------------------------------
__global__ __launch_bounds__(256)
void prep_fused(const float* __restrict__ Ws,
                const float* __restrict__ tr,
                const float* __restrict__ Wr,
                const float* __restrict__ Wx,
                __nv_bfloat16* __restrict__ Bhi,
                __nv_bfloat16* __restrict__ Blo,
                float* __restrict__ dual_part)
{
    const int bx = blockIdx.x;
    if (bx < 512) {
        const int z = bx >> 8, kc = (bx >> 6) & 3, rem = bx & 63;
        const int col0 = (rem & 7) * 64, row0 = (rem >> 3) * 64;
        float* outp = dual_part + (size_t)(z * 4 + kc) * HB;
        if (z == 0)
            gemm_k<false>(tr, Wr, outp, row0, col0, kc * 128);
        else
            gemm_k<true>(tr, Wx, outp, row0, col0, kc * 128);
    } else {
        const int base = (bx - 512) * 1024 + threadIdx.x * 4;
        #pragma unroll
        for (int i = 0; i < 4; i++) {
            const int j = base + i;
            const int n = j >> 8, p = j & 255;
            __nv_bfloat162 h2, l2;
            split1(Ws[(2 * p) * Hh + n],     h2.x, l2.x);
            split1(Ws[(2 * p + 1) * Hh + n], h2.y, l2.y);
            ((__nv_bfloat162*)Bhi)[(size_t)n * (Hh / 2) + p] = h2;
            ((__nv_bfloat162*)Blo)[(size_t)n * (Hh / 2) + p] = l2;
        }
    }
}

// ---------------------------------------------------------------------------
// score kernel (byte-identical logic to R11/R12; WR sums 4 split-K partials)
// ---------------------------------------------------------------------------
#define A_W     4096u
#define PLANE_W 2048u
#define STG_W   (A_W + 2u * PLANE_W)
#define NSTG    3
#define SM_W    (NSTG * STG_W + 512)
#define SM_BYTES (SM_W * 4)

__global__ __launch_bounds__(256, 2)
void score_mma(const float* __restrict__ Afp,
               const __nv_bfloat16* __restrict__ Bhi,
               const __nv_bfloat16* __restrict__ Blo,
               const float* __restrict__ dual_part,
               const float* __restrict__ wvec,
               float* __restrict__ scores_part)
{
    extern __shared__ uint32_t smw[];
    float* WRs = (float*)(smw + NSTG * STG_W);
    float* WVs = WRs + 128;
    float* sp2 = WVs + 128;

    const int tid  = threadIdx.x;
    const int lane = tid & 31, wid = tid >> 5;
    const int wm = wid & 3, wn = wid >> 2;
    const int g  = lane >> 2, tg = lane & 3;
    const int col0 = blockIdx.x * 128;
    const int row0 = blockIdx.y * 128;
    const int b    = row0 >> 8;

    if (tid < 128) {
        const size_t o = (size_t)b * Hh + col0 + tid;
        WRs[tid] = ((dual_part[o] + dual_part[HB + o])
                  + (dual_part[2 * (size_t)HB + o] + dual_part[3 * (size_t)HB + o]));
        WVs[tid] = wvec[col0 + tid];
    }

    const uint32_t sbase = smem_u32(smw);

    const uint32_t b_row = (lane & 7) | (((lane >> 4) & 1) << 3);
    const uint32_t b_chk = (lane >> 3) & 1;
    const uint32_t wsel = ((2u * tg) & 3u) * 4u;
    const uint32_t cbase = (uint32_t)(tg >> 1);

    auto load_stage = [&](int kk, int slot) {
        const uint32_t db = sbase + (uint32_t)slot * (STG_W * 4);
        #pragma unroll
        for (int i = 0; i < 8; i++) {
            const int idx = tid + 256 * i;
            if (i < 4) {
                const uint32_t r = (uint32_t)(idx >> 3), c = (uint32_t)(idx & 7);
                cp16(db + swzA(r, c),
                     Afp + (size_t)(row0 + r) * Hh + kk * 32 + c * 4);
            } else {
                const int j = idx - 1024;
                const int plane = j >> 9;
                const uint32_t r = (uint32_t)((j >> 2) & 127), c = (uint32_t)(j & 3);
                const __nv_bfloat16* src = (plane == 0 ? Bhi : Blo)
                                           + (size_t)(col0 + r) * Hh + kk * 32 + c * 8;
                cp16(db + (A_W + plane * PLANE_W) * 4u + swz(r, c), src);
            }
        }
        asm volatile("cp.async.commit_group;" ::: "memory");
    };

    load_stage(0, 0);
    load_stage(1, 1);

    float acc[2][8][4];
    #pragma unroll
    for (int mt = 0; mt < 2; mt++)
        #pragma unroll
        for (int nt = 0; nt < 8; nt++)
            #pragma unroll
            for (int c = 0; c < 4; c++) acc[mt][nt][c] = 0.0f;

    #pragma unroll 1
    for (int kk = 0; kk < 16; kk++) {
        if (kk < 15) asm volatile("cp.async.wait_group 1;" ::: "memory");
        else         asm volatile("cp.async.wait_group 0;" ::: "memory");
        __syncthreads();

        if (kk + 2 < 16) load_stage(kk + 2, (kk + 2) % 3);

        const uint32_t stg  = sbase + (uint32_t)(kk % 3) * (STG_W * 4);
        const uint32_t pA   = stg;
        const uint32_t pBhi = stg + A_W * 4;
        const uint32_t pBlo = stg + (A_W + PLANE_W) * 4;

        #pragma unroll
        for (int ks = 0; ks < 2; ks++) {
            uint32_t ahi[2][4], alo[2][4];
            const uint32_t c0 = 4u * ks + cbase;
            const uint32_t c1 = c0 + 2u;
            #pragma unroll
            for (int mt = 0; mt < 2; mt++) {
                const uint32_t rb = (uint32_t)(wm * 32 + mt * 16);
                const uint32_t r0 = rb + g, r1 = rb + 8 + g;
                const uint32_t x0 = pA + r0 * 128u + ((c0 ^ g) << 4) + wsel;
                const uint32_t x1 = pA + r1 * 128u + ((c0 ^ g) << 4) + wsel;
                const uint32_t x2 = pA + r0 * 128u + ((c1 ^ g) << 4) + wsel;
                const uint32_t x3 = pA + r1 * 128u + ((c1 ^ g) << 4) + wsel;
                cvt_pair(lds64(x0), ahi[mt][0], alo[mt][0]);
                cvt_pair(lds64(x1), ahi[mt][1], alo[mt][1]);
                cvt_pair(lds64(x2), ahi[mt][2], alo[mt][2]);
                cvt_pair(lds64(x3), ahi[mt][3], alo[mt][3]);
            }
            #pragma unroll
            for (int ntp = 0; ntp < 4; ntp++) {
                const uint32_t r = wn * 64 + ntp * 16 + b_row;
                const uint32_t off = swz(r, ks * 2 + b_chk);
                uint32_t bh[4], bl[4];
                ldsm4(bh, pBhi + off);
                ldsm4(bl, pBlo + off);
                #pragma unroll
                for (int half = 0; half < 2; half++) {
                    const int nt = ntp * 2 + half;
                    const uint32_t b0h = bh[half * 2], b1h = bh[half * 2 + 1];
                    const uint32_t b0l = bl[half * 2], b1l = bl[half * 2 + 1];
                    #pragma unroll
                    for (int mt = 0; mt < 2; mt++) {
                        mma_bf16(acc[mt][nt], ahi[mt], b0l, b1l);
                        mma_bf16(acc[mt][nt], alo[mt], b0h, b1h);
                        mma_bf16(acc[mt][nt], ahi[mt], b0h, b1h);
                    }
                }
            }
        }
    }

    #pragma unroll
    for (int mt = 0; mt < 2; mt++) {
        float plo = 0.0f, phi = 0.0f;
        #pragma unroll
        for (int nt = 0; nt < 8; nt++) {
            const int c0 = wn * 64 + nt * 8 + 2 * tg;
            const int c1 = c0 + 1;
            plo += tanh_fast(acc[mt][nt][0] + WRs[c0]) * WVs[c0]
                 + tanh_fast(acc[mt][nt][1] + WRs[c1]) * WVs[c1];
            phi += tanh_fast(acc[mt][nt][2] + WRs[c0]) * WVs[c0]
                 + tanh_fast(acc[mt][nt][3] + WRs[c1]) * WVs[c1];
        }
        plo += __shfl_xor_sync(0xFFFFFFFFu, plo, 1);
        plo += __shfl_xor_sync(0xFFFFFFFFu, plo, 2);
        phi += __shfl_xor_sync(0xFFFFFFFFu, phi, 1);
        phi += __shfl_xor_sync(0xFFFFFFFFu, phi, 2);
        if (tg == 0) {
            sp2[wn * 128 + wm * 32 + mt * 16 + g]     = plo;
            sp2[wn * 128 + wm * 32 + mt * 16 + 8 + g] = phi;
        }
    }
    __syncthreads();
    if (tid < 128)
        scores_part[(size_t)blockIdx.x * (Bsz * Nn) + row0 + tid] =
            sp2[tid] + sp2[128 + tid];
}

// ---------------------------------------------------------------------------
// Per-batch softmax + resp_s (unchanged)
// ---------------------------------------------------------------------------
__global__ __launch_bounds__(256)
void softmax_weight_kernel(const float* __restrict__ scores_part,
                           const float* __restrict__ mask,
                           const float* __restrict__ emb,
                           float* __restrict__ alpha_out,
                           float* __restrict__ resps)
{
    const int b = blockIdx.x;
    const int half = blockIdx.y;
    const int tid = threadIdx.x;
    __shared__ float sa[256];
    __shared__ float red[256];

    const size_t i = (size_t)b * Nn + tid;
    float s = scores_part[i];
    s += scores_part[(size_t)(Bsz * Nn) + i];
    s += scores_part[(size_t)(2 * Bsz * Nn) + i];
    s += scores_part[(size_t)(3 * Bsz * Nn) + i];
    const float t = s * mask[i];

    red[tid] = t; __syncthreads();
    #pragma unroll
    for (int st = 128; st > 0; st >>= 1) {
        if (tid < st) red[tid] = fmaxf(red[tid], red[tid + st]);
        __syncthreads();
    }
    const float m = red[0];
    __syncthreads();

    const float e = __expf(t - m);
    red[tid] = e; __syncthreads();
    #pragma unroll
    for (int st = 128; st > 0; st >>= 1) {
        if (tid < st) red[tid] += red[tid + st];
        __syncthreads();
    }
    const float a = e / red[0];

    if (half == 0) alpha_out[i] = a;
    sa[tid] = a;
    __syncthreads();

    const int h = half * 256 + tid;
    const float* eb = emb + (size_t)b * Nn * Hh + h;
    float c0 = 0.f, c1 = 0.f, c2 = 0.f, c3 = 0.f;
    float c4 = 0.f, c5 = 0.f, c6 = 0.f, c7 = 0.f;
    #pragma unroll 1
    for (int n = 0; n < Nn; n += 8) {
        c0 = fmaf(sa[n    ], eb[(size_t)(n    ) * Hh], c0);
        c1 = fmaf(sa[n + 1], eb[(size_t)(n + 1) * Hh], c1);
        c2 = fmaf(sa[n + 2], eb[(size_t)(n + 2) * Hh], c2);
        c3 = fmaf(sa[n + 3], eb[(size_t)(n + 3) * Hh], c3);
        c4 = fmaf(sa[n + 4], eb[(size_t)(n + 4) * Hh], c4);
        c5 = fmaf(sa[n + 5], eb[(size_t)(n + 5) * Hh], c5);
        c6 = fmaf(sa[n + 6], eb[(size_t)(n + 6) * Hh], c6);
        c7 = fmaf(sa[n + 7], eb[(size_t)(n + 7) * Hh], c7);
    }
    resps[b * Hh + h] = ((c0 + c1) + (c2 + c3)) + ((c4 + c5) + (c6 + c7));
}

// ---------------------------------------------------------------------------
// Final GEMM split-K4: partial = presps @ Wp^T over 128-wide K chunk
// grid (8 col, 8 row, 4 kc); 64x64 tiles.
// ---------------------------------------------------------------------------
__global__ __launch_bounds__(256)
void gemm_final_k(const float* __restrict__ A,
                  const float* __restrict__ B,
                  float* __restrict__ fin_part)
{
    const int kc = blockIdx.z;
    gemm_k<true>(A, B, fin_part + (size_t)kc * HB,
                 blockIdx.y * 64, blockIdx.x * 64, kc * 128);
}

// combine: out = tanh(sum fin partials + sum rx partials)   (deterministic)
__global__ __launch_bounds__(512)
void combine_final(const float* __restrict__ fin_part,
                   const float* __restrict__ dual_part,
                   float* __restrict__ out)
{
    const size_t idx = (size_t)blockIdx.x * 512 + threadIdx.x;
    float f = ((fin_part[idx] + fin_part[HB + idx])
             + (fin_part[2 * (size_t)HB + idx] + fin_part[3 * (size_t)HB + idx]));
    const float* rx = dual_part + 4 * (size_t)HB;
    float r = ((rx[idx] + rx[HB + idx])
             + (rx[2 * (size_t)HB + idx] + rx[3 * (size_t)HB + idx]));
    out[idx] = tanhf(f + r);
}

// ---------------------------------------------------------------------------
extern "C" void kernel_launch(void* const* d_in, const int* in_sizes, int n_in,
                              void* d_out, int out_size)
{
    const float* spk  = (const float*)d_in[0];
    const float* mask = (const float*)d_in[1];
    const float* tr   = (const float*)d_in[2];
    const float* Ws   = (const float*)d_in[3];
    const float* Wr   = (const float*)d_in[4];
    const float* w    = (const float*)d_in[5];
    const float* Wp   = (const float*)d_in[6];
    const float* Wx   = (const float*)d_in[7];

    float* out = (float*)d_out;
    float* resp_out  = out;
    float* alpha_out = out + Bsz * Hh;

    float *pspart, *presps, *pdual, *pfin;
    __nv_bfloat16 *pBhi, *pBlo;
    cudaGetSymbolAddress((void**)&pspart, g_scores_part);
    cudaGetSymbolAddress((void**)&presps, g_resps);
    cudaGetSymbolAddress((void**)&pdual, g_dual_part);
    cudaGetSymbolAddress((void**)&pfin, g_fin_part);
    cudaGetSymbolAddress((void**)&pBhi, g_Bhi);
    cudaGetSymbolAddress((void**)&pBlo, g_Blo);

    static bool attr_set = false;
    if (!attr_set) {
        cudaFuncSetAttribute(score_mma,
                             cudaFuncAttributeMaxDynamicSharedMemorySize,
                             SM_BYTES);
        attr_set = true;
    }

    prep_fused<<<640, 256>>>(Ws, tr, Wr, Wx, pBhi, pBlo, pdual);
    score_mma<<<dim3(4, 1024), 256, SM_BYTES>>>(spk, pBhi, pBlo,
                                                pdual, w, pspart);
    softmax_weight_kernel<<<dim3(512, 2), 256>>>(pspart, mask, spk,
                                                 alpha_out, presps);
    gemm_final_k<<<dim3(8, 8, 4), 256>>>(presps, Wp, pfin);
    combine_final<<<512, 512>>>(pfin, pdual, resp_out);
}